// round 1
// baseline (speedup 1.0000x reference)
#include <cuda_runtime.h>
#include <cstddef>

#define B_  2
#define T_  2048
#define C_  2048
#define H_  16
#define HK_ 4
#define HD_ 128
#define BT_ (B_*T_)

// ---------------- scratch (device globals; no allocation allowed) ----------------
__device__ float g_qt[(size_t)BT_ * 2048];   // x@Wq  [B*T, H*HD]
__device__ float g_kt[(size_t)BT_ * 512];    // x@Wk  [B*T, HK*HD]
__device__ float g_vt[(size_t)BT_ * 512];    // x@Wv
__device__ float g_q [(size_t)B_*H_ *T_*HD_]; // roped, [B,H,T,HD]
__device__ float g_k [(size_t)B_*HK_*T_*HD_]; // roped, [B,HK,T,HD]
__device__ float g_v [(size_t)B_*HK_*T_*HD_]; // [B,HK,T,HD]
__device__ float g_y [(size_t)BT_ * C_];      // attention out, [B*T, C]

// ---------------- generic tiled fp32 GEMM: C = A[M,K] @ W[K,N] (+bias) ----------------
// BM=BN=64, BK=16, 256 threads, 4x4 microtile per thread.
__global__ void gemm_bias_kernel(const float* __restrict__ A, const float* __restrict__ W,
                                 const float* __restrict__ bias, float* __restrict__ Cout,
                                 int M, int N, int K) {
    __shared__ float As[16][64];   // [k][m]
    __shared__ float Ws[16][64];   // [k][n]
    const int tid = threadIdx.x;
    const int bn = blockIdx.x * 64;
    const int bm = blockIdx.y * 64;
    const int tx = tid & 15, ty = tid >> 4;

    const int mload = tid >> 2, kq = tid & 3;   // A tile loader mapping
    const int kw = tid >> 4,   nq = tid & 15;   // W tile loader mapping

    float acc[4][4] = {};

    for (int k0 = 0; k0 < K; k0 += 16) {
        float4 av = *(const float4*)(A + (size_t)(bm + mload) * K + k0 + kq * 4);
        float4 wv = *(const float4*)(W + (size_t)(k0 + kw) * N + bn + nq * 4);
        __syncthreads();
        As[kq*4 + 0][mload] = av.x;
        As[kq*4 + 1][mload] = av.y;
        As[kq*4 + 2][mload] = av.z;
        As[kq*4 + 3][mload] = av.w;
        *(float4*)&Ws[kw][nq * 4] = wv;
        __syncthreads();
#pragma unroll
        for (int kk = 0; kk < 16; kk++) {
            float ar[4], wr[4];
            *(float4*)ar = *(float4*)&As[kk][ty * 4];
            *(float4*)wr = *(float4*)&Ws[kk][tx * 4];
#pragma unroll
            for (int i = 0; i < 4; i++)
#pragma unroll
                for (int j = 0; j < 4; j++)
                    acc[i][j] += ar[i] * wr[j];
        }
    }

#pragma unroll
    for (int i = 0; i < 4; i++) {
        float4 o;
        float b0 = bias ? bias[bn + tx*4 + 0] : 0.f;
        float b1 = bias ? bias[bn + tx*4 + 1] : 0.f;
        float b2 = bias ? bias[bn + tx*4 + 2] : 0.f;
        float b3 = bias ? bias[bn + tx*4 + 3] : 0.f;
        o.x = acc[i][0] + b0;
        o.y = acc[i][1] + b1;
        o.z = acc[i][2] + b2;
        o.w = acc[i][3] + b3;
        *(float4*)(Cout + (size_t)(bm + ty*4 + i) * N + bn + tx * 4) = o;
    }
}

// ---------------- RoPE + transpose [B,T,Hn,HD] -> [B,Hn,T,HD] ----------------
__global__ void rope_transpose_kernel(const float* __restrict__ in, const float* __restrict__ cosp,
                                      const float* __restrict__ sinp, float* __restrict__ outp, int Hn) {
    int idx = blockIdx.x * blockDim.x + threadIdx.x;
    int total = B_ * T_ * Hn * 64;
    if (idx >= total) return;
    int d = idx & 63;
    int h = (idx >> 6) % Hn;
    int t = (idx / (64 * Hn)) % T_;
    int b = idx / (64 * Hn * T_);
    size_t ibase = ((size_t)(b * T_ + t) * Hn + h) * HD_;
    float x1 = in[ibase + d];
    float x2 = in[ibase + d + 64];
    size_t cbase = (size_t)(b * T_ + t) * HD_;
    float c1 = cosp[cbase + d],      s1 = sinp[cbase + d];
    float c2 = cosp[cbase + d + 64], s2 = sinp[cbase + d + 64];
    size_t obase = (((size_t)b * Hn + h) * T_ + t) * HD_;
    outp[obase + d]      = x1 * c1 - x2 * s1;
    outp[obase + d + 64] = x2 * c2 + x1 * s2;
}

__global__ void transpose_v_kernel(const float* __restrict__ in, float* __restrict__ outp) {
    int idx = blockIdx.x * blockDim.x + threadIdx.x;
    int total = B_ * T_ * HK_ * HD_;
    if (idx >= total) return;
    int d  = idx & 127;
    int hk = (idx >> 7) & 3;
    int t  = (idx >> 9) % T_;
    int b  = idx / (512 * T_);
    outp[(((size_t)b * HK_ + hk) * T_ + t) * HD_ + d] =
        in[((size_t)(b * T_ + t) * HK_ + hk) * HD_ + d];
}

// ---------------- flash attention, fp32, 64-query tile, 64-key tiles ----------------
// smem: Qs[128][64] (Q^T), Ks[128][64] (K^T), Vs[64][128], Ss[64][65], row stats
#define ATTN_SMEM_FLOATS (64*128*3 + 64*65 + 3*64)
#define ATTN_SMEM_BYTES  (ATTN_SMEM_FLOATS * 4)

__global__ void attn_kernel(const float* __restrict__ gq, const float* __restrict__ gk,
                            const float* __restrict__ gv, float* __restrict__ gy) {
    extern __shared__ float sm[];
    float* Qs   = sm;               // [128][64] transposed
    float* Ks   = Qs + 64 * 128;    // [128][64] transposed
    float* Vs   = Ks + 64 * 128;    // [64][128] row-major
    float* Ss   = Vs + 64 * 128;    // [64][65] padded
    float* rowm = Ss + 64 * 65;
    float* rowl = rowm + 64;
    float* rowsc = rowl + 64;

    const int qt = blockIdx.x, h = blockIdx.y, b = blockIdx.z;
    const int g = h >> 2;           // GQA group (N_REP = 4)
    const int tid = threadIdx.x;

    const float* qbase = gq + (((size_t)b * H_  + h) * T_ + (size_t)qt * 64) * HD_;
    const float* kbase = gk + ((size_t)b * HK_ + g) * T_ * HD_;
    const float* vbase = gv + ((size_t)b * HK_ + g) * T_ * HD_;

    // load Q tile transposed: Qs[kk][r]
    for (int L = tid; L < 2048; L += 256) {
        int row = L >> 5;
        int c4  = (L & 31) << 2;
        float4 qv = *(const float4*)(qbase + row * 128 + c4);
        Qs[(c4 + 0) * 64 + row] = qv.x;
        Qs[(c4 + 1) * 64 + row] = qv.y;
        Qs[(c4 + 2) * 64 + row] = qv.z;
        Qs[(c4 + 3) * 64 + row] = qv.w;
    }
    if (tid < 64) { rowm[tid] = -1e30f; rowl[tid] = 0.f; }

    float acc[4][8];
#pragma unroll
    for (int i = 0; i < 4; i++)
#pragma unroll
        for (int c = 0; c < 8; c++) acc[i][c] = 0.f;

    const int r0  = (tid >> 4) * 4;   // 4 rows
    const int c0s = (tid & 15) * 4;   // 4 score cols
    const int c0v = (tid & 15) * 8;   // 8 output cols

    for (int kt = 0; kt <= qt; kt++) {
        __syncthreads();   // protect Ks/Vs reuse
        const float* kb = kbase + (size_t)kt * 64 * 128;
        const float* vb = vbase + (size_t)kt * 64 * 128;
        for (int L = tid; L < 2048; L += 256) {
            int row = L >> 5;
            int c4  = (L & 31) << 2;
            float4 kv = *(const float4*)(kb + row * 128 + c4);
            Ks[(c4 + 0) * 64 + row] = kv.x;
            Ks[(c4 + 1) * 64 + row] = kv.y;
            Ks[(c4 + 2) * 64 + row] = kv.z;
            Ks[(c4 + 3) * 64 + row] = kv.w;
            *(float4*)(Vs + row * 128 + c4) = *(const float4*)(vb + row * 128 + c4);
        }
        __syncthreads();

        // S = Q K^T (4x4 per thread)
        float s[4][4] = {};
#pragma unroll 4
        for (int kk = 0; kk < 128; kk++) {
            float ar[4], br[4];
#pragma unroll
            for (int i = 0; i < 4; i++) ar[i] = Qs[kk * 64 + r0 + i];
#pragma unroll
            for (int j = 0; j < 4; j++) br[j] = Ks[kk * 64 + c0s + j];
#pragma unroll
            for (int i = 0; i < 4; i++)
#pragma unroll
                for (int j = 0; j < 4; j++)
                    s[i][j] += ar[i] * br[j];
        }
        const float SC = 0.08838834764831845f;  // 1/sqrt(128)
#pragma unroll
        for (int i = 0; i < 4; i++)
#pragma unroll
            for (int j = 0; j < 4; j++) {
                int qi = qt * 64 + r0 + i;
                int kj = kt * 64 + c0s + j;
                Ss[(r0 + i) * 65 + c0s + j] = (kj <= qi) ? s[i][j] * SC : -1e30f;
            }
        __syncthreads();

        // online softmax per row (64 threads)
        if (tid < 64) {
            int r = tid;
            float mold = rowm[r], tmax = mold;
            for (int j = 0; j < 64; j++) tmax = fmaxf(tmax, Ss[r * 65 + j]);
            float sc = __expf(mold - tmax);
            float sum = 0.f;
            for (int j = 0; j < 64; j++) {
                float p = __expf(Ss[r * 65 + j] - tmax);
                Ss[r * 65 + j] = p;
                sum += p;
            }
            rowl[r] = rowl[r] * sc + sum;
            rowm[r] = tmax;
            rowsc[r] = sc;
        }
        __syncthreads();

        // rescale + accumulate P V
#pragma unroll
        for (int i = 0; i < 4; i++) {
            float scl = rowsc[r0 + i];
#pragma unroll
            for (int c = 0; c < 8; c++) acc[i][c] *= scl;
        }
        for (int j = 0; j < 64; j++) {
            float4 v0 = *(float4*)(Vs + j * 128 + c0v);
            float4 v1 = *(float4*)(Vs + j * 128 + c0v + 4);
#pragma unroll
            for (int i = 0; i < 4; i++) {
                float p = Ss[(r0 + i) * 65 + j];
                acc[i][0] += p * v0.x;  acc[i][1] += p * v0.y;
                acc[i][2] += p * v0.z;  acc[i][3] += p * v0.w;
                acc[i][4] += p * v1.x;  acc[i][5] += p * v1.y;
                acc[i][6] += p * v1.z;  acc[i][7] += p * v1.w;
            }
        }
    }
    __syncthreads();

    // write out to [B*T, C] with head offset
#pragma unroll
    for (int i = 0; i < 4; i++) {
        float inv = 1.f / rowl[r0 + i];
        float* op = gy + ((size_t)b * T_ + (size_t)qt * 64 + r0 + i) * C_ + h * HD_ + c0v;
        float4 o0, o1;
        o0.x = acc[i][0] * inv;  o0.y = acc[i][1] * inv;
        o0.z = acc[i][2] * inv;  o0.w = acc[i][3] * inv;
        o1.x = acc[i][4] * inv;  o1.y = acc[i][5] * inv;
        o1.z = acc[i][6] * inv;  o1.w = acc[i][7] * inv;
        *(float4*)op       = o0;
        *(float4*)(op + 4) = o1;
    }
}

// ---------------- launch ----------------
extern "C" void kernel_launch(void* const* d_in, const int* in_sizes, int n_in,
                              void* d_out, int out_size) {
    const float* x    = (const float*)d_in[0];
    const float* cosp = (const float*)d_in[1];
    const float* sinp = (const float*)d_in[2];
    const float* Wq   = (const float*)d_in[3];
    const float* bq   = (const float*)d_in[4];
    const float* Wk   = (const float*)d_in[5];
    const float* bk   = (const float*)d_in[6];
    const float* Wv   = (const float*)d_in[7];
    const float* bv   = (const float*)d_in[8];
    const float* Wo   = (const float*)d_in[9];
    float* out = (float*)d_out;

    float *qt, *ktp, *vtp, *q, *k, *v, *y;
    cudaGetSymbolAddress((void**)&qt,  g_qt);
    cudaGetSymbolAddress((void**)&ktp, g_kt);
    cudaGetSymbolAddress((void**)&vtp, g_vt);
    cudaGetSymbolAddress((void**)&q,   g_q);
    cudaGetSymbolAddress((void**)&k,   g_k);
    cudaGetSymbolAddress((void**)&v,   g_v);
    cudaGetSymbolAddress((void**)&y,   g_y);

    dim3 blk(256);

    // QKV projections
    gemm_bias_kernel<<<dim3(2048/64, BT_/64), blk>>>(x, Wq, bq, qt,  BT_, 2048, C_);
    gemm_bias_kernel<<<dim3(512/64,  BT_/64), blk>>>(x, Wk, bk, ktp, BT_, 512,  C_);
    gemm_bias_kernel<<<dim3(512/64,  BT_/64), blk>>>(x, Wv, bv, vtp, BT_, 512,  C_);

    // RoPE + layout transforms
    {
        int nq = B_ * T_ * H_ * 64;
        rope_transpose_kernel<<<(nq + 255)/256, 256>>>(qt, cosp, sinp, q, H_);
        int nk = B_ * T_ * HK_ * 64;
        rope_transpose_kernel<<<(nk + 255)/256, 256>>>(ktp, cosp, sinp, k, HK_);
        int nv = B_ * T_ * HK_ * HD_;
        transpose_v_kernel<<<(nv + 255)/256, 256>>>(vtp, v);
    }

    // attention
    cudaFuncSetAttribute(attn_kernel, cudaFuncAttributeMaxDynamicSharedMemorySize, ATTN_SMEM_BYTES);
    attn_kernel<<<dim3(T_/64, H_, B_), blk, ATTN_SMEM_BYTES>>>(q, k, v, y);

    // output projection -> d_out
    gemm_bias_kernel<<<dim3(2048/64, BT_/64), blk>>>(y, Wo, nullptr, out, BT_, C_, C_);
}

// round 2
// speedup vs baseline: 1.1866x; 1.1866x over previous
#include <cuda_runtime.h>
#include <cstddef>

#define B_  2
#define T_  2048
#define C_  2048
#define H_  16
#define HK_ 4
#define HD_ 128
#define BT_ (B_*T_)

// ---------------- scratch (device globals; no allocation allowed) ----------------
__device__ float g_qt[(size_t)BT_ * 2048];   // x@Wq  [B*T, H*HD]
__device__ float g_kt[(size_t)BT_ * 512];    // x@Wk  [B*T, HK*HD]
__device__ float g_vt[(size_t)BT_ * 512];    // x@Wv
__device__ float g_q [(size_t)B_*H_ *T_*HD_]; // roped, [B,H,T,HD]
__device__ float g_k [(size_t)B_*HK_*T_*HD_]; // roped, [B,HK,T,HD]
__device__ float g_v [(size_t)B_*HK_*T_*HD_]; // [B,HK,T,HD]
__device__ float g_y [(size_t)BT_ * C_];      // attention out, [B*T, C]

// ---------------- 3xTF32 tensor-core GEMM: C = A[M,K] @ W[K,N] (+bias) ----------------
// BM=BN=128, BK=16, 256 threads (8 warps: 4 in M x 2 in N), m16n8k8 tf32 mma.
// Error-compensated: A=Ah+Al, W=Wh+Wl; accumulate Ah*Wh + Al*Wh + Ah*Wl in fp32.

__device__ __forceinline__ unsigned f2tf(float x) {
    unsigned r; asm("cvt.rna.tf32.f32 %0, %1;" : "=r"(r) : "f"(x)); return r;
}

#define MMA_TF32(Cacc, Afrag, b0, b1)                                              \
    asm volatile("mma.sync.aligned.m16n8k8.row.col.f32.tf32.tf32.f32 "             \
        "{%0,%1,%2,%3}, {%4,%5,%6,%7}, {%8,%9}, {%0,%1,%2,%3};"                    \
        : "+f"(Cacc[0]), "+f"(Cacc[1]), "+f"(Cacc[2]), "+f"(Cacc[3])               \
        : "r"(Afrag[0]), "r"(Afrag[1]), "r"(Afrag[2]), "r"(Afrag[3]),              \
          "r"(b0), "r"(b1))

__global__ __launch_bounds__(256) void gemm_tf32x3_kernel(
    const float* __restrict__ A, const float* __restrict__ W,
    const float* __restrict__ bias, float* __restrict__ Cout,
    int M, int N, int K)
{
    __shared__ float As_h[128][20];   // [m][k], stride 20 -> conflict-free frag loads
    __shared__ float As_l[128][20];
    __shared__ float Ws_h[16][132];   // [k][n], stride 132 -> <=2-way on frag loads
    __shared__ float Ws_l[16][132];

    const int tid  = threadIdx.x;
    const int bm   = blockIdx.y * 128;
    const int bn   = blockIdx.x * 128;
    const int lane = tid & 31, warp = tid >> 5;
    const int wm   = (warp & 3) * 32;    // warp tile: 32 rows
    const int wn   = (warp >> 2) * 64;   // warp tile: 64 cols
    const int g    = lane >> 2, tg = lane & 3;

    // gmem loader mappings
    const int ar0 = tid >> 2, ac4 = (tid & 3) * 4;     // A: rows ar0, ar0+64
    const int wk0 = tid >> 5, wn4 = (tid & 31) * 4;    // W: k rows wk0, wk0+8

    float4 aR[2], wR[2];
    float c[2][8][4];
#pragma unroll
    for (int mt = 0; mt < 2; mt++)
#pragma unroll
        for (int nt = 0; nt < 8; nt++)
#pragma unroll
            for (int i = 0; i < 4; i++) c[mt][nt][i] = 0.f;

    auto loadG = [&](int k0) {
        aR[0] = *(const float4*)(A + (size_t)(bm + ar0)      * K + k0 + ac4);
        aR[1] = *(const float4*)(A + (size_t)(bm + ar0 + 64) * K + k0 + ac4);
        wR[0] = *(const float4*)(W + (size_t)(k0 + wk0)      * N + bn + wn4);
        wR[1] = *(const float4*)(W + (size_t)(k0 + wk0 + 8)  * N + bn + wn4);
    };

    auto storeS = [&]() {
#pragma unroll
        for (int i = 0; i < 2; i++) {
            int r = ar0 + i * 64;
            float v[4] = {aR[i].x, aR[i].y, aR[i].z, aR[i].w};
            float4 h, l;
            float* hp = &h.x; float* lp = &l.x;
#pragma unroll
            for (int j = 0; j < 4; j++) {
                float hi = __uint_as_float(f2tf(v[j]));
                hp[j] = hi;
                lp[j] = __uint_as_float(f2tf(v[j] - hi));
            }
            *(float4*)&As_h[r][ac4] = h;
            *(float4*)&As_l[r][ac4] = l;
        }
#pragma unroll
        for (int i = 0; i < 2; i++) {
            int kk = wk0 + i * 8;
            float v[4] = {wR[i].x, wR[i].y, wR[i].z, wR[i].w};
            float4 h, l;
            float* hp = &h.x; float* lp = &l.x;
#pragma unroll
            for (int j = 0; j < 4; j++) {
                float hi = __uint_as_float(f2tf(v[j]));
                hp[j] = hi;
                lp[j] = __uint_as_float(f2tf(v[j] - hi));
            }
            *(float4*)&Ws_h[kk][wn4] = h;
            *(float4*)&Ws_l[kk][wn4] = l;
        }
    };

    auto computeTile = [&]() {
#pragma unroll
        for (int ks = 0; ks < 2; ks++) {
            const int kb = ks * 8;
            unsigned ah[2][4], al[2][4];
#pragma unroll
            for (int mt = 0; mt < 2; mt++) {
                int r = wm + mt * 16;
                ah[mt][0] = __float_as_uint(As_h[r + g    ][kb + tg    ]);
                ah[mt][1] = __float_as_uint(As_h[r + g + 8][kb + tg    ]);
                ah[mt][2] = __float_as_uint(As_h[r + g    ][kb + tg + 4]);
                ah[mt][3] = __float_as_uint(As_h[r + g + 8][kb + tg + 4]);
                al[mt][0] = __float_as_uint(As_l[r + g    ][kb + tg    ]);
                al[mt][1] = __float_as_uint(As_l[r + g + 8][kb + tg    ]);
                al[mt][2] = __float_as_uint(As_l[r + g    ][kb + tg + 4]);
                al[mt][3] = __float_as_uint(As_l[r + g + 8][kb + tg + 4]);
            }
#pragma unroll
            for (int nt = 0; nt < 8; nt++) {
                int cn = wn + nt * 8 + g;
                unsigned bh0 = __float_as_uint(Ws_h[kb + tg    ][cn]);
                unsigned bh1 = __float_as_uint(Ws_h[kb + tg + 4][cn]);
                unsigned bl0 = __float_as_uint(Ws_l[kb + tg    ][cn]);
                unsigned bl1 = __float_as_uint(Ws_l[kb + tg + 4][cn]);
#pragma unroll
                for (int mt = 0; mt < 2; mt++) {
                    MMA_TF32(c[mt][nt], ah[mt], bh0, bh1);
                    MMA_TF32(c[mt][nt], al[mt], bh0, bh1);
                    MMA_TF32(c[mt][nt], ah[mt], bl0, bl1);
                }
            }
        }
    };

    loadG(0);
    storeS();
    __syncthreads();
    for (int k0 = 16; k0 < K; k0 += 16) {
        loadG(k0);
        computeTile();
        __syncthreads();
        storeS();
        __syncthreads();
    }
    computeTile();

    // epilogue
#pragma unroll
    for (int mt = 0; mt < 2; mt++) {
        int r0 = bm + wm + mt * 16 + g;
#pragma unroll
        for (int nt = 0; nt < 8; nt++) {
            int col = bn + wn + nt * 8 + tg * 2;
            float b0 = 0.f, b1 = 0.f;
            if (bias) { b0 = bias[col]; b1 = bias[col + 1]; }
            float2 v0 = {c[mt][nt][0] + b0, c[mt][nt][1] + b1};
            float2 v1 = {c[mt][nt][2] + b0, c[mt][nt][3] + b1};
            *(float2*)(Cout + (size_t)r0 * N + col)       = v0;
            *(float2*)(Cout + (size_t)(r0 + 8) * N + col) = v1;
        }
    }
}

// ---------------- RoPE + transpose [B,T,Hn,HD] -> [B,Hn,T,HD] ----------------
__global__ void rope_transpose_kernel(const float* __restrict__ in, const float* __restrict__ cosp,
                                      const float* __restrict__ sinp, float* __restrict__ outp, int Hn) {
    int idx = blockIdx.x * blockDim.x + threadIdx.x;
    int total = B_ * T_ * Hn * 64;
    if (idx >= total) return;
    int d = idx & 63;
    int h = (idx >> 6) % Hn;
    int t = (idx / (64 * Hn)) % T_;
    int b = idx / (64 * Hn * T_);
    size_t ibase = ((size_t)(b * T_ + t) * Hn + h) * HD_;
    float x1 = in[ibase + d];
    float x2 = in[ibase + d + 64];
    size_t cbase = (size_t)(b * T_ + t) * HD_;
    float c1 = cosp[cbase + d],      s1 = sinp[cbase + d];
    float c2 = cosp[cbase + d + 64], s2 = sinp[cbase + d + 64];
    size_t obase = (((size_t)b * Hn + h) * T_ + t) * HD_;
    outp[obase + d]      = x1 * c1 - x2 * s1;
    outp[obase + d + 64] = x2 * c2 + x1 * s2;
}

__global__ void transpose_v_kernel(const float* __restrict__ in, float* __restrict__ outp) {
    int idx = blockIdx.x * blockDim.x + threadIdx.x;
    int total = B_ * T_ * HK_ * HD_;
    if (idx >= total) return;
    int d  = idx & 127;
    int hk = (idx >> 7) & 3;
    int t  = (idx >> 9) % T_;
    int b  = idx / (512 * T_);
    outp[(((size_t)b * HK_ + hk) * T_ + t) * HD_ + d] =
        in[((size_t)(b * T_ + t) * HK_ + hk) * HD_ + d];
}

// ---------------- flash attention, fp32, 64-query tile, 64-key tiles ----------------
#define ATTN_SMEM_FLOATS (64*128*3 + 64*65 + 3*64)
#define ATTN_SMEM_BYTES  (ATTN_SMEM_FLOATS * 4)

__global__ void attn_kernel(const float* __restrict__ gq, const float* __restrict__ gk,
                            const float* __restrict__ gv, float* __restrict__ gy) {
    extern __shared__ float sm[];
    float* Qs   = sm;               // [128][64] transposed
    float* Ks   = Qs + 64 * 128;    // [128][64] transposed
    float* Vs   = Ks + 64 * 128;    // [64][128] row-major
    float* Ss   = Vs + 64 * 128;    // [64][65] padded
    float* rowm = Ss + 64 * 65;
    float* rowl = rowm + 64;
    float* rowsc = rowl + 64;

    const int qt = blockIdx.x, h = blockIdx.y, b = blockIdx.z;
    const int g = h >> 2;           // GQA group (N_REP = 4)
    const int tid = threadIdx.x;

    const float* qbase = gq + (((size_t)b * H_  + h) * T_ + (size_t)qt * 64) * HD_;
    const float* kbase = gk + ((size_t)b * HK_ + g) * T_ * HD_;
    const float* vbase = gv + ((size_t)b * HK_ + g) * T_ * HD_;

    for (int L = tid; L < 2048; L += 256) {
        int row = L >> 5;
        int c4  = (L & 31) << 2;
        float4 qv = *(const float4*)(qbase + row * 128 + c4);
        Qs[(c4 + 0) * 64 + row] = qv.x;
        Qs[(c4 + 1) * 64 + row] = qv.y;
        Qs[(c4 + 2) * 64 + row] = qv.z;
        Qs[(c4 + 3) * 64 + row] = qv.w;
    }
    if (tid < 64) { rowm[tid] = -1e30f; rowl[tid] = 0.f; }

    float acc[4][8];
#pragma unroll
    for (int i = 0; i < 4; i++)
#pragma unroll
        for (int c = 0; c < 8; c++) acc[i][c] = 0.f;

    const int r0  = (tid >> 4) * 4;
    const int c0s = (tid & 15) * 4;
    const int c0v = (tid & 15) * 8;

    for (int kt = 0; kt <= qt; kt++) {
        __syncthreads();
        const float* kb = kbase + (size_t)kt * 64 * 128;
        const float* vb = vbase + (size_t)kt * 64 * 128;
        for (int L = tid; L < 2048; L += 256) {
            int row = L >> 5;
            int c4  = (L & 31) << 2;
            float4 kv = *(const float4*)(kb + row * 128 + c4);
            Ks[(c4 + 0) * 64 + row] = kv.x;
            Ks[(c4 + 1) * 64 + row] = kv.y;
            Ks[(c4 + 2) * 64 + row] = kv.z;
            Ks[(c4 + 3) * 64 + row] = kv.w;
            *(float4*)(Vs + row * 128 + c4) = *(const float4*)(vb + row * 128 + c4);
        }
        __syncthreads();

        float s[4][4] = {};
#pragma unroll 4
        for (int kk = 0; kk < 128; kk++) {
            float ar[4], br[4];
#pragma unroll
            for (int i = 0; i < 4; i++) ar[i] = Qs[kk * 64 + r0 + i];
#pragma unroll
            for (int j = 0; j < 4; j++) br[j] = Ks[kk * 64 + c0s + j];
#pragma unroll
            for (int i = 0; i < 4; i++)
#pragma unroll
                for (int j = 0; j < 4; j++)
                    s[i][j] += ar[i] * br[j];
        }
        const float SC = 0.08838834764831845f;
#pragma unroll
        for (int i = 0; i < 4; i++)
#pragma unroll
            for (int j = 0; j < 4; j++) {
                int qi = qt * 64 + r0 + i;
                int kj = kt * 64 + c0s + j;
                Ss[(r0 + i) * 65 + c0s + j] = (kj <= qi) ? s[i][j] * SC : -1e30f;
            }
        __syncthreads();

        if (tid < 64) {
            int r = tid;
            float mold = rowm[r], tmax = mold;
            for (int j = 0; j < 64; j++) tmax = fmaxf(tmax, Ss[r * 65 + j]);
            float sc = __expf(mold - tmax);
            float sum = 0.f;
            for (int j = 0; j < 64; j++) {
                float p = __expf(Ss[r * 65 + j] - tmax);
                Ss[r * 65 + j] = p;
                sum += p;
            }
            rowl[r] = rowl[r] * sc + sum;
            rowm[r] = tmax;
            rowsc[r] = sc;
        }
        __syncthreads();

#pragma unroll
        for (int i = 0; i < 4; i++) {
            float scl = rowsc[r0 + i];
#pragma unroll
            for (int c = 0; c < 8; c++) acc[i][c] *= scl;
        }
        for (int j = 0; j < 64; j++) {
            float4 v0 = *(float4*)(Vs + j * 128 + c0v);
            float4 v1 = *(float4*)(Vs + j * 128 + c0v + 4);
#pragma unroll
            for (int i = 0; i < 4; i++) {
                float p = Ss[(r0 + i) * 65 + j];
                acc[i][0] += p * v0.x;  acc[i][1] += p * v0.y;
                acc[i][2] += p * v0.z;  acc[i][3] += p * v0.w;
                acc[i][4] += p * v1.x;  acc[i][5] += p * v1.y;
                acc[i][6] += p * v1.z;  acc[i][7] += p * v1.w;
            }
        }
    }
    __syncthreads();

#pragma unroll
    for (int i = 0; i < 4; i++) {
        float inv = 1.f / rowl[r0 + i];
        float* op = gy + ((size_t)b * T_ + (size_t)qt * 64 + r0 + i) * C_ + h * HD_ + c0v;
        float4 o0, o1;
        o0.x = acc[i][0] * inv;  o0.y = acc[i][1] * inv;
        o0.z = acc[i][2] * inv;  o0.w = acc[i][3] * inv;
        o1.x = acc[i][4] * inv;  o1.y = acc[i][5] * inv;
        o1.z = acc[i][6] * inv;  o1.w = acc[i][7] * inv;
        *(float4*)op       = o0;
        *(float4*)(op + 4) = o1;
    }
}

// ---------------- launch ----------------
extern "C" void kernel_launch(void* const* d_in, const int* in_sizes, int n_in,
                              void* d_out, int out_size) {
    const float* x    = (const float*)d_in[0];
    const float* cosp = (const float*)d_in[1];
    const float* sinp = (const float*)d_in[2];
    const float* Wq   = (const float*)d_in[3];
    const float* bq   = (const float*)d_in[4];
    const float* Wk   = (const float*)d_in[5];
    const float* bk   = (const float*)d_in[6];
    const float* Wv   = (const float*)d_in[7];
    const float* bv   = (const float*)d_in[8];
    const float* Wo   = (const float*)d_in[9];
    float* out = (float*)d_out;

    float *qt, *ktp, *vtp, *q, *k, *v, *y;
    cudaGetSymbolAddress((void**)&qt,  g_qt);
    cudaGetSymbolAddress((void**)&ktp, g_kt);
    cudaGetSymbolAddress((void**)&vtp, g_vt);
    cudaGetSymbolAddress((void**)&q,   g_q);
    cudaGetSymbolAddress((void**)&k,   g_k);
    cudaGetSymbolAddress((void**)&v,   g_v);
    cudaGetSymbolAddress((void**)&y,   g_y);

    dim3 blk(256);

    // QKV projections (tensor cores, 3xTF32)
    gemm_tf32x3_kernel<<<dim3(2048/128, BT_/128), blk>>>(x, Wq, bq, qt,  BT_, 2048, C_);
    gemm_tf32x3_kernel<<<dim3(512/128,  BT_/128), blk>>>(x, Wk, bk, ktp, BT_, 512,  C_);
    gemm_tf32x3_kernel<<<dim3(512/128,  BT_/128), blk>>>(x, Wv, bv, vtp, BT_, 512,  C_);

    // RoPE + layout transforms
    {
        int nq = B_ * T_ * H_ * 64;
        rope_transpose_kernel<<<(nq + 255)/256, 256>>>(qt, cosp, sinp, q, H_);
        int nk = B_ * T_ * HK_ * 64;
        rope_transpose_kernel<<<(nk + 255)/256, 256>>>(ktp, cosp, sinp, k, HK_);
        int nv = B_ * T_ * HK_ * HD_;
        transpose_v_kernel<<<(nv + 255)/256, 256>>>(vtp, v);
    }

    // attention (fp32)
    cudaFuncSetAttribute(attn_kernel, cudaFuncAttributeMaxDynamicSharedMemorySize, ATTN_SMEM_BYTES);
    attn_kernel<<<dim3(T_/64, H_, B_), blk, ATTN_SMEM_BYTES>>>(q, k, v, y);

    // output projection -> d_out (tensor cores, 3xTF32)
    gemm_tf32x3_kernel<<<dim3(2048/128, BT_/128), blk>>>(y, Wo, nullptr, out, BT_, C_, C_);
}

// round 4
// speedup vs baseline: 1.1890x; 1.0020x over previous
#include <cuda_runtime.h>
#include <cstddef>

#define B_  2
#define T_  2048
#define C_  2048
#define H_  16
#define HK_ 4
#define HD_ 128
#define BT_ (B_*T_)

// ---------------- scratch (device globals; no allocation allowed) ----------------
__device__ float g_qt[(size_t)BT_ * 2048];   // x@Wq  [B*T, H*HD]
__device__ float g_kt[(size_t)BT_ * 512];    // x@Wk  [B*T, HK*HD]
__device__ float g_vt[(size_t)BT_ * 512];    // x@Wv
__device__ float g_q [(size_t)B_*H_ *T_*HD_]; // roped, [B,H,T,HD]
__device__ float g_k [(size_t)B_*HK_*T_*HD_]; // roped, [B,HK,T,HD]
__device__ float g_v [(size_t)B_*HK_*T_*HD_]; // [B,HK,T,HD]
__device__ float g_y [(size_t)BT_ * C_];      // attention out, [B*T, C]

// ---------------- 3xTF32 tensor-core GEMM: C = A[M,K] @ W[K,N] (+bias) ----------------
// BM=BN=128, BK=16, 256 threads (8 warps: 4 in M x 2 in N), m16n8k8 tf32 mma.
// Error-compensated: A=Ah+Al, W=Wh+Wl; accumulate Ah*Wh + Al*Wh + Ah*Wl in fp32.

__device__ __forceinline__ unsigned f2tf(float x) {
    unsigned r; asm("cvt.rna.tf32.f32 %0, %1;" : "=r"(r) : "f"(x)); return r;
}

#define MMA_TF32(Cacc, Afrag, b0, b1)                                              \
    asm volatile("mma.sync.aligned.m16n8k8.row.col.f32.tf32.tf32.f32 "             \
        "{%0,%1,%2,%3}, {%4,%5,%6,%7}, {%8,%9}, {%0,%1,%2,%3};"                    \
        : "+f"(Cacc[0]), "+f"(Cacc[1]), "+f"(Cacc[2]), "+f"(Cacc[3])               \
        : "r"(Afrag[0]), "r"(Afrag[1]), "r"(Afrag[2]), "r"(Afrag[3]),              \
          "r"(b0), "r"(b1))

__global__ __launch_bounds__(256) void gemm_tf32x3_kernel(
    const float* __restrict__ A, const float* __restrict__ W,
    const float* __restrict__ bias, float* __restrict__ Cout,
    int M, int N, int K)
{
    __shared__ float As_h[128][20];   // [m][k], stride 20 -> conflict-free frag loads
    __shared__ float As_l[128][20];
    __shared__ float Ws_h[16][132];   // [k][n], stride 132 -> <=2-way on frag loads
    __shared__ float Ws_l[16][132];

    const int tid  = threadIdx.x;
    const int bm   = blockIdx.y * 128;
    const int bn   = blockIdx.x * 128;
    const int lane = tid & 31, warp = tid >> 5;
    const int wm   = (warp & 3) * 32;    // warp tile: 32 rows
    const int wn   = (warp >> 2) * 64;   // warp tile: 64 cols
    const int g    = lane >> 2, tg = lane & 3;

    // gmem loader mappings
    const int ar0 = tid >> 2, ac4 = (tid & 3) * 4;     // A: rows ar0, ar0+64
    const int wk0 = tid >> 5, wn4 = (tid & 31) * 4;    // W: k rows wk0, wk0+8

    float4 aR[2], wR[2];
    float c[2][8][4];
#pragma unroll
    for (int mt = 0; mt < 2; mt++)
#pragma unroll
        for (int nt = 0; nt < 8; nt++)
#pragma unroll
            for (int i = 0; i < 4; i++) c[mt][nt][i] = 0.f;

    auto loadG = [&](int k0) {
        aR[0] = *(const float4*)(A + (size_t)(bm + ar0)      * K + k0 + ac4);
        aR[1] = *(const float4*)(A + (size_t)(bm + ar0 + 64) * K + k0 + ac4);
        wR[0] = *(const float4*)(W + (size_t)(k0 + wk0)      * N + bn + wn4);
        wR[1] = *(const float4*)(W + (size_t)(k0 + wk0 + 8)  * N + bn + wn4);
    };

    auto storeS = [&]() {
#pragma unroll
        for (int i = 0; i < 2; i++) {
            int r = ar0 + i * 64;
            float v[4] = {aR[i].x, aR[i].y, aR[i].z, aR[i].w};
            float4 h, l;
            float* hp = &h.x; float* lp = &l.x;
#pragma unroll
            for (int j = 0; j < 4; j++) {
                float hi = __uint_as_float(f2tf(v[j]));
                hp[j] = hi;
                lp[j] = __uint_as_float(f2tf(v[j] - hi));
            }
            *(float4*)&As_h[r][ac4] = h;
            *(float4*)&As_l[r][ac4] = l;
        }
#pragma unroll
        for (int i = 0; i < 2; i++) {
            int kk = wk0 + i * 8;
            float v[4] = {wR[i].x, wR[i].y, wR[i].z, wR[i].w};
            float4 h, l;
            float* hp = &h.x; float* lp = &l.x;
#pragma unroll
            for (int j = 0; j < 4; j++) {
                float hi = __uint_as_float(f2tf(v[j]));
                hp[j] = hi;
                lp[j] = __uint_as_float(f2tf(v[j] - hi));
            }
            *(float4*)&Ws_h[kk][wn4] = h;
            *(float4*)&Ws_l[kk][wn4] = l;
        }
    };

    auto computeTile = [&]() {
#pragma unroll
        for (int ks = 0; ks < 2; ks++) {
            const int kb = ks * 8;
            unsigned ah[2][4], al[2][4];
#pragma unroll
            for (int mt = 0; mt < 2; mt++) {
                int r = wm + mt * 16;
                ah[mt][0] = __float_as_uint(As_h[r + g    ][kb + tg    ]);
                ah[mt][1] = __float_as_uint(As_h[r + g + 8][kb + tg    ]);
                ah[mt][2] = __float_as_uint(As_h[r + g    ][kb + tg + 4]);
                ah[mt][3] = __float_as_uint(As_h[r + g + 8][kb + tg + 4]);
                al[mt][0] = __float_as_uint(As_l[r + g    ][kb + tg    ]);
                al[mt][1] = __float_as_uint(As_l[r + g + 8][kb + tg    ]);
                al[mt][2] = __float_as_uint(As_l[r + g    ][kb + tg + 4]);
                al[mt][3] = __float_as_uint(As_l[r + g + 8][kb + tg + 4]);
            }
#pragma unroll
            for (int nt = 0; nt < 8; nt++) {
                int cn = wn + nt * 8 + g;
                unsigned bh0 = __float_as_uint(Ws_h[kb + tg    ][cn]);
                unsigned bh1 = __float_as_uint(Ws_h[kb + tg + 4][cn]);
                unsigned bl0 = __float_as_uint(Ws_l[kb + tg    ][cn]);
                unsigned bl1 = __float_as_uint(Ws_l[kb + tg + 4][cn]);
#pragma unroll
                for (int mt = 0; mt < 2; mt++) {
                    MMA_TF32(c[mt][nt], ah[mt], bh0, bh1);
                    MMA_TF32(c[mt][nt], al[mt], bh0, bh1);
                    MMA_TF32(c[mt][nt], ah[mt], bl0, bl1);
                }
            }
        }
    };

    loadG(0);
    storeS();
    __syncthreads();
    for (int k0 = 16; k0 < K; k0 += 16) {
        loadG(k0);
        computeTile();
        __syncthreads();
        storeS();
        __syncthreads();
    }
    computeTile();

    // epilogue
#pragma unroll
    for (int mt = 0; mt < 2; mt++) {
        int r0 = bm + wm + mt * 16 + g;
#pragma unroll
        for (int nt = 0; nt < 8; nt++) {
            int col = bn + wn + nt * 8 + tg * 2;
            float b0 = 0.f, b1 = 0.f;
            if (bias) { b0 = bias[col]; b1 = bias[col + 1]; }
            float2 v0 = {c[mt][nt][0] + b0, c[mt][nt][1] + b1};
            float2 v1 = {c[mt][nt][2] + b0, c[mt][nt][3] + b1};
            *(float2*)(Cout + (size_t)r0 * N + col)       = v0;
            *(float2*)(Cout + (size_t)(r0 + 8) * N + col) = v1;
        }
    }
}

// ---------------- RoPE + transpose [B,T,Hn,HD] -> [B,Hn,T,HD] ----------------
__global__ void rope_transpose_kernel(const float* __restrict__ in, const float* __restrict__ cosp,
                                      const float* __restrict__ sinp, float* __restrict__ outp, int Hn) {
    int idx = blockIdx.x * blockDim.x + threadIdx.x;
    int total = B_ * T_ * Hn * 64;
    if (idx >= total) return;
    int d = idx & 63;
    int h = (idx >> 6) % Hn;
    int t = (idx / (64 * Hn)) % T_;
    int b = idx / (64 * Hn * T_);
    size_t ibase = ((size_t)(b * T_ + t) * Hn + h) * HD_;
    float x1 = in[ibase + d];
    float x2 = in[ibase + d + 64];
    size_t cbase = (size_t)(b * T_ + t) * HD_;
    float c1 = cosp[cbase + d],      s1 = sinp[cbase + d];
    float c2 = cosp[cbase + d + 64], s2 = sinp[cbase + d + 64];
    size_t obase = (((size_t)b * Hn + h) * T_ + t) * HD_;
    outp[obase + d]      = x1 * c1 - x2 * s1;
    outp[obase + d + 64] = x2 * c2 + x1 * s2;
}

__global__ void transpose_v_kernel(const float* __restrict__ in, float* __restrict__ outp) {
    int idx = blockIdx.x * blockDim.x + threadIdx.x;
    int total = B_ * T_ * HK_ * HD_;
    if (idx >= total) return;
    int d  = idx & 127;
    int hk = (idx >> 7) & 3;
    int t  = (idx >> 9) % T_;
    int b  = idx / (512 * T_);
    outp[(((size_t)b * HK_ + hk) * T_ + t) * HD_ + d] =
        in[((size_t)(b * T_ + t) * HK_ + hk) * HD_ + d];
}

// ---------------- flash attention, fp32, 64-query tile, 64-key tiles ----------------
#define ATTN_SMEM_FLOATS (64*128*3 + 64*65 + 3*64)
#define ATTN_SMEM_BYTES  (ATTN_SMEM_FLOATS * 4)

__global__ void attn_kernel(const float* __restrict__ gq, const float* __restrict__ gk,
                            const float* __restrict__ gv, float* __restrict__ gy) {
    extern __shared__ float sm[];
    float* Qs   = sm;               // [128][64] transposed
    float* Ks   = Qs + 64 * 128;    // [128][64] transposed
    float* Vs   = Ks + 64 * 128;    // [64][128] row-major
    float* Ss   = Vs + 64 * 128;    // [64][65] padded
    float* rowm = Ss + 64 * 65;
    float* rowl = rowm + 64;
    float* rowsc = rowl + 64;

    const int qt = blockIdx.x, h = blockIdx.y, b = blockIdx.z;
    const int g = h >> 2;           // GQA group (N_REP = 4)
    const int tid = threadIdx.x;

    const float* qbase = gq + (((size_t)b * H_  + h) * T_ + (size_t)qt * 64) * HD_;
    const float* kbase = gk + ((size_t)b * HK_ + g) * T_ * HD_;
    const float* vbase = gv + ((size_t)b * HK_ + g) * T_ * HD_;

    for (int L = tid; L < 2048; L += 256) {
        int row = L >> 5;
        int c4  = (L & 31) << 2;
        float4 qv = *(const float4*)(qbase + row * 128 + c4);
        Qs[(c4 + 0) * 64 + row] = qv.x;
        Qs[(c4 + 1) * 64 + row] = qv.y;
        Qs[(c4 + 2) * 64 + row] = qv.z;
        Qs[(c4 + 3) * 64 + row] = qv.w;
    }
    if (tid < 64) { rowm[tid] = -1e30f; rowl[tid] = 0.f; }

    float acc[4][8];
#pragma unroll
    for (int i = 0; i < 4; i++)
#pragma unroll
        for (int c = 0; c < 8; c++) acc[i][c] = 0.f;

    const int r0  = (tid >> 4) * 4;
    const int c0s = (tid & 15) * 4;
    const int c0v = (tid & 15) * 8;

    for (int kt = 0; kt <= qt; kt++) {
        __syncthreads();
        const float* kb = kbase + (size_t)kt * 64 * 128;
        const float* vb = vbase + (size_t)kt * 64 * 128;
        for (int L = tid; L < 2048; L += 256) {
            int row = L >> 5;
            int c4  = (L & 31) << 2;
            float4 kv = *(const float4*)(kb + row * 128 + c4);
            Ks[(c4 + 0) * 64 + row] = kv.x;
            Ks[(c4 + 1) * 64 + row] = kv.y;
            Ks[(c4 + 2) * 64 + row] = kv.z;
            Ks[(c4 + 3) * 64 + row] = kv.w;
            *(float4*)(Vs + row * 128 + c4) = *(const float4*)(vb + row * 128 + c4);
        }
        __syncthreads();

        float s[4][4] = {};
#pragma unroll 4
        for (int kk = 0; kk < 128; kk++) {
            float ar[4], br[4];
#pragma unroll
            for (int i = 0; i < 4; i++) ar[i] = Qs[kk * 64 + r0 + i];
#pragma unroll
            for (int j = 0; j < 4; j++) br[j] = Ks[kk * 64 + c0s + j];
#pragma unroll
            for (int i = 0; i < 4; i++)
#pragma unroll
                for (int j = 0; j < 4; j++)
                    s[i][j] += ar[i] * br[j];
        }
        const float SC = 0.08838834764831845f;
#pragma unroll
        for (int i = 0; i < 4; i++)
#pragma unroll
            for (int j = 0; j < 4; j++) {
                int qi = qt * 64 + r0 + i;
                int kj = kt * 64 + c0s + j;
                Ss[(r0 + i) * 65 + c0s + j] = (kj <= qi) ? s[i][j] * SC : -1e30f;
            }
        __syncthreads();

        if (tid < 64) {
            int r = tid;
            float mold = rowm[r], tmax = mold;
            for (int j = 0; j < 64; j++) tmax = fmaxf(tmax, Ss[r * 65 + j]);
            float sc = __expf(mold - tmax);
            float sum = 0.f;
            for (int j = 0; j < 64; j++) {
                float p = __expf(Ss[r * 65 + j] - tmax);
                Ss[r * 65 + j] = p;
                sum += p;
            }
            rowl[r] = rowl[r] * sc + sum;
            rowm[r] = tmax;
            rowsc[r] = sc;
        }
        __syncthreads();

#pragma unroll
        for (int i = 0; i < 4; i++) {
            float scl = rowsc[r0 + i];
#pragma unroll
            for (int c = 0; c < 8; c++) acc[i][c] *= scl;
        }
        for (int j = 0; j < 64; j++) {
            float4 v0 = *(float4*)(Vs + j * 128 + c0v);
            float4 v1 = *(float4*)(Vs + j * 128 + c0v + 4);
#pragma unroll
            for (int i = 0; i < 4; i++) {
                float p = Ss[(r0 + i) * 65 + j];
                acc[i][0] += p * v0.x;  acc[i][1] += p * v0.y;
                acc[i][2] += p * v0.z;  acc[i][3] += p * v0.w;
                acc[i][4] += p * v1.x;  acc[i][5] += p * v1.y;
                acc[i][6] += p * v1.z;  acc[i][7] += p * v1.w;
            }
        }
    }
    __syncthreads();

#pragma unroll
    for (int i = 0; i < 4; i++) {
        float inv = 1.f / rowl[r0 + i];
        float* op = gy + ((size_t)b * T_ + (size_t)qt * 64 + r0 + i) * C_ + h * HD_ + c0v;
        float4 o0, o1;
        o0.x = acc[i][0] * inv;  o0.y = acc[i][1] * inv;
        o0.z = acc[i][2] * inv;  o0.w = acc[i][3] * inv;
        o1.x = acc[i][4] * inv;  o1.y = acc[i][5] * inv;
        o1.z = acc[i][6] * inv;  o1.w = acc[i][7] * inv;
        *(float4*)op       = o0;
        *(float4*)(op + 4) = o1;
    }
}

// ---------------- launch ----------------
extern "C" void kernel_launch(void* const* d_in, const int* in_sizes, int n_in,
                              void* d_out, int out_size) {
    const float* x    = (const float*)d_in[0];
    const float* cosp = (const float*)d_in[1];
    const float* sinp = (const float*)d_in[2];
    const float* Wq   = (const float*)d_in[3];
    const float* bq   = (const float*)d_in[4];
    const float* Wk   = (const float*)d_in[5];
    const float* bk   = (const float*)d_in[6];
    const float* Wv   = (const float*)d_in[7];
    const float* bv   = (const float*)d_in[8];
    const float* Wo   = (const float*)d_in[9];
    float* out = (float*)d_out;

    float *qt, *ktp, *vtp, *q, *k, *v, *y;
    cudaGetSymbolAddress((void**)&qt,  g_qt);
    cudaGetSymbolAddress((void**)&ktp, g_kt);
    cudaGetSymbolAddress((void**)&vtp, g_vt);
    cudaGetSymbolAddress((void**)&q,   g_q);
    cudaGetSymbolAddress((void**)&k,   g_k);
    cudaGetSymbolAddress((void**)&v,   g_v);
    cudaGetSymbolAddress((void**)&y,   g_y);

    dim3 blk(256);

    // QKV projections (tensor cores, 3xTF32)
    gemm_tf32x3_kernel<<<dim3(2048/128, BT_/128), blk>>>(x, Wq, bq, qt,  BT_, 2048, C_);
    gemm_tf32x3_kernel<<<dim3(512/128,  BT_/128), blk>>>(x, Wk, bk, ktp, BT_, 512,  C_);
    gemm_tf32x3_kernel<<<dim3(512/128,  BT_/128), blk>>>(x, Wv, bv, vtp, BT_, 512,  C_);

    // RoPE + layout transforms
    {
        int nq = B_ * T_ * H_ * 64;
        rope_transpose_kernel<<<(nq + 255)/256, 256>>>(qt, cosp, sinp, q, H_);
        int nk = B_ * T_ * HK_ * 64;
        rope_transpose_kernel<<<(nk + 255)/256, 256>>>(ktp, cosp, sinp, k, HK_);
        int nv = B_ * T_ * HK_ * HD_;
        transpose_v_kernel<<<(nv + 255)/256, 256>>>(vtp, v);
    }

    // attention (fp32)
    cudaFuncSetAttribute(attn_kernel, cudaFuncAttributeMaxDynamicSharedMemorySize, ATTN_SMEM_BYTES);
    attn_kernel<<<dim3(T_/64, H_, B_), blk, ATTN_SMEM_BYTES>>>(q, k, v, y);

    // output projection -> d_out (tensor cores, 3xTF32)
    gemm_tf32x3_kernel<<<dim3(2048/128, BT_/128), blk>>>(y, Wo, nullptr, out, BT_, C_, C_);
}

// round 10
// speedup vs baseline: 1.4206x; 1.1949x over previous
#include <cuda_runtime.h>
#include <cstddef>

#define B_  2
#define T_  2048
#define C_  2048
#define H_  16
#define HK_ 4
#define HD_ 128
#define BT_ (B_*T_)

__device__ float g_qt[(size_t)BT_ * 2048];
__device__ float g_kt[(size_t)BT_ * 512];
__device__ float g_vt[(size_t)BT_ * 512];
__device__ float g_q [(size_t)B_*H_ *T_*HD_];
__device__ float g_k [(size_t)B_*HK_*T_*HD_];
__device__ float g_v [(size_t)B_*HK_*T_*HD_];
__device__ float g_y [(size_t)BT_ * C_];

__device__ __forceinline__ unsigned f2tf(float x) {
    unsigned r; asm("cvt.rna.tf32.f32 %0, %1;" : "=r"(r) : "f"(x)); return r;
}

#define MMA_TF32(Cacc, Afrag, b0, b1)                                              \
    asm volatile("mma.sync.aligned.m16n8k8.row.col.f32.tf32.tf32.f32 "             \
        "{%0,%1,%2,%3}, {%4,%5,%6,%7}, {%8,%9}, {%0,%1,%2,%3};"                    \
        : "+f"(Cacc[0]), "+f"(Cacc[1]), "+f"(Cacc[2]), "+f"(Cacc[3])               \
        : "r"(Afrag[0]), "r"(Afrag[1]), "r"(Afrag[2]), "r"(Afrag[3]),              \
          "r"(b0), "r"(b1))

// ---------------- 3xTF32 tensor-core GEMM (unchanged from R2) ----------------
__global__ __launch_bounds__(256) void gemm_tf32x3_kernel(
    const float* __restrict__ A, const float* __restrict__ W,
    const float* __restrict__ bias, float* __restrict__ Cout,
    int M, int N, int K)
{
    __shared__ float As_h[128][20];
    __shared__ float As_l[128][20];
    __shared__ float Ws_h[16][132];
    __shared__ float Ws_l[16][132];

    const int tid  = threadIdx.x;
    const int bm   = blockIdx.y * 128;
    const int bn   = blockIdx.x * 128;
    const int lane = tid & 31, warp = tid >> 5;
    const int wm   = (warp & 3) * 32;
    const int wn   = (warp >> 2) * 64;
    const int g    = lane >> 2, tg = lane & 3;

    const int ar0 = tid >> 2, ac4 = (tid & 3) * 4;
    const int wk0 = tid >> 5, wn4 = (tid & 31) * 4;

    float4 aR[2], wR[2];
    float c[2][8][4];
#pragma unroll
    for (int mt = 0; mt < 2; mt++)
#pragma unroll
        for (int nt = 0; nt < 8; nt++)
#pragma unroll
            for (int i = 0; i < 4; i++) c[mt][nt][i] = 0.f;

    auto loadG = [&](int k0) {
        aR[0] = *(const float4*)(A + (size_t)(bm + ar0)      * K + k0 + ac4);
        aR[1] = *(const float4*)(A + (size_t)(bm + ar0 + 64) * K + k0 + ac4);
        wR[0] = *(const float4*)(W + (size_t)(k0 + wk0)      * N + bn + wn4);
        wR[1] = *(const float4*)(W + (size_t)(k0 + wk0 + 8)  * N + bn + wn4);
    };

    auto storeS = [&]() {
#pragma unroll
        for (int i = 0; i < 2; i++) {
            int r = ar0 + i * 64;
            float v[4] = {aR[i].x, aR[i].y, aR[i].z, aR[i].w};
            float4 h, l;
            float* hp = &h.x; float* lp = &l.x;
#pragma unroll
            for (int j = 0; j < 4; j++) {
                float hi = __uint_as_float(f2tf(v[j]));
                hp[j] = hi;
                lp[j] = __uint_as_float(f2tf(v[j] - hi));
            }
            *(float4*)&As_h[r][ac4] = h;
            *(float4*)&As_l[r][ac4] = l;
        }
#pragma unroll
        for (int i = 0; i < 2; i++) {
            int kk = wk0 + i * 8;
            float v[4] = {wR[i].x, wR[i].y, wR[i].z, wR[i].w};
            float4 h, l;
            float* hp = &h.x; float* lp = &l.x;
#pragma unroll
            for (int j = 0; j < 4; j++) {
                float hi = __uint_as_float(f2tf(v[j]));
                hp[j] = hi;
                lp[j] = __uint_as_float(f2tf(v[j] - hi));
            }
            *(float4*)&Ws_h[kk][wn4] = h;
            *(float4*)&Ws_l[kk][wn4] = l;
        }
    };

    auto computeTile = [&]() {
#pragma unroll
        for (int ks = 0; ks < 2; ks++) {
            const int kb = ks * 8;
            unsigned ah[2][4], al[2][4];
#pragma unroll
            for (int mt = 0; mt < 2; mt++) {
                int r = wm + mt * 16;
                ah[mt][0] = __float_as_uint(As_h[r + g    ][kb + tg    ]);
                ah[mt][1] = __float_as_uint(As_h[r + g + 8][kb + tg    ]);
                ah[mt][2] = __float_as_uint(As_h[r + g    ][kb + tg + 4]);
                ah[mt][3] = __float_as_uint(As_h[r + g + 8][kb + tg + 4]);
                al[mt][0] = __float_as_uint(As_l[r + g    ][kb + tg    ]);
                al[mt][1] = __float_as_uint(As_l[r + g + 8][kb + tg    ]);
                al[mt][2] = __float_as_uint(As_l[r + g    ][kb + tg + 4]);
                al[mt][3] = __float_as_uint(As_l[r + g + 8][kb + tg + 4]);
            }
#pragma unroll
            for (int nt = 0; nt < 8; nt++) {
                int cn = wn + nt * 8 + g;
                unsigned bh0 = __float_as_uint(Ws_h[kb + tg    ][cn]);
                unsigned bh1 = __float_as_uint(Ws_h[kb + tg + 4][cn]);
                unsigned bl0 = __float_as_uint(Ws_l[kb + tg    ][cn]);
                unsigned bl1 = __float_as_uint(Ws_l[kb + tg + 4][cn]);
#pragma unroll
                for (int mt = 0; mt < 2; mt++) {
                    MMA_TF32(c[mt][nt], ah[mt], bh0, bh1);
                    MMA_TF32(c[mt][nt], al[mt], bh0, bh1);
                    MMA_TF32(c[mt][nt], ah[mt], bl0, bl1);
                }
            }
        }
    };

    loadG(0);
    storeS();
    __syncthreads();
    for (int k0 = 16; k0 < K; k0 += 16) {
        loadG(k0);
        computeTile();
        __syncthreads();
        storeS();
        __syncthreads();
    }
    computeTile();

#pragma unroll
    for (int mt = 0; mt < 2; mt++) {
        int r0 = bm + wm + mt * 16 + g;
#pragma unroll
        for (int nt = 0; nt < 8; nt++) {
            int col = bn + wn + nt * 8 + tg * 2;
            float b0 = 0.f, b1 = 0.f;
            if (bias) { b0 = bias[col]; b1 = bias[col + 1]; }
            float2 v0 = {c[mt][nt][0] + b0, c[mt][nt][1] + b1};
            float2 v1 = {c[mt][nt][2] + b0, c[mt][nt][3] + b1};
            *(float2*)(Cout + (size_t)r0 * N + col)       = v0;
            *(float2*)(Cout + (size_t)(r0 + 8) * N + col) = v1;
        }
    }
}

// ---------------- RoPE + transposes (unchanged) ----------------
__global__ void rope_transpose_kernel(const float* __restrict__ in, const float* __restrict__ cosp,
                                      const float* __restrict__ sinp, float* __restrict__ outp, int Hn) {
    int idx = blockIdx.x * blockDim.x + threadIdx.x;
    int total = B_ * T_ * Hn * 64;
    if (idx >= total) return;
    int d = idx & 63;
    int h = (idx >> 6) % Hn;
    int t = (idx / (64 * Hn)) % T_;
    int b = idx / (64 * Hn * T_);
    size_t ibase = ((size_t)(b * T_ + t) * Hn + h) * HD_;
    float x1 = in[ibase + d];
    float x2 = in[ibase + d + 64];
    size_t cbase = (size_t)(b * T_ + t) * HD_;
    float c1 = cosp[cbase + d],      s1 = sinp[cbase + d];
    float c2 = cosp[cbase + d + 64], s2 = sinp[cbase + d + 64];
    size_t obase = (((size_t)b * Hn + h) * T_ + t) * HD_;
    outp[obase + d]      = x1 * c1 - x2 * s1;
    outp[obase + d + 64] = x2 * c2 + x1 * s2;
}

__global__ void transpose_v_kernel(const float* __restrict__ in, float* __restrict__ outp) {
    int idx = blockIdx.x * blockDim.x + threadIdx.x;
    int total = B_ * T_ * HK_ * HD_;
    if (idx >= total) return;
    int d  = idx & 127;
    int hk = (idx >> 7) & 3;
    int t  = (idx >> 9) % T_;
    int b  = idx / (512 * T_);
    outp[(((size_t)b * HK_ + hk) * T_ + t) * HD_ + d] =
        in[((size_t)(b * T_ + t) * HK_ + hk) * HD_ + d];
}

// ---------------- flash attention on tf32x3 mma ----------------
// smem: Qs[64][132], Ks[128][68] (K^T), Vs[64][132], Ss[64][68], stats
#define AT_QS   0
#define AT_KS   (64*132)
#define AT_VS   (AT_KS + 128*68)
#define AT_SS   (AT_VS + 64*132)
#define AT_RM   (AT_SS + 64*68)
#define AT_FLOATS (AT_RM + 3*64)
#define AT_BYTES  (AT_FLOATS * 4)

__global__ __launch_bounds__(256) void attn_mma_kernel(
    const float* __restrict__ gq, const float* __restrict__ gk,
    const float* __restrict__ gv, float* __restrict__ gy)
{
    extern __shared__ float sm[];
    float* Qs   = sm + AT_QS;
    float* Ks   = sm + AT_KS;
    float* Vs   = sm + AT_VS;
    float* Ss   = sm + AT_SS;
    float* rowm = sm + AT_RM;
    float* rowl = rowm + 64;
    float* rowsc = rowl + 64;

    const int qt = blockIdx.x, h = blockIdx.y, b = blockIdx.z;
    const int grp = h >> 2;
    const int tid = threadIdx.x, lane = tid & 31, warp = tid >> 5;
    const int gg = lane >> 2, tg = lane & 3;
    const int wmS = (warp & 3) * 16, wnS = (warp >> 2) * 32;   // QK: 16x32
    const int wnP = (warp >> 2) * 64;                          // PV: 16x64 (same wm)
    const float SC = 0.08838834764831845f;

    const float* qbase = gq + (((size_t)b * H_  + h)   * T_ + (size_t)qt * 64) * HD_;
    const float* kbase = gk + ((size_t)b * HK_ + grp) * T_ * HD_;
    const float* vbase = gv + ((size_t)b * HK_ + grp) * T_ * HD_;

    // load Q tile [64][128] row-major into Qs (stride 132)
    for (int L = tid; L < 2048; L += 256) {
        int row = L >> 5, c4 = (L & 31) << 2;
        *(float4*)(Qs + row * 132 + c4) = *(const float4*)(qbase + row * 128 + c4);
    }
    if (tid < 64) { rowm[tid] = -1e30f; rowl[tid] = 0.f; }

    float c2[8][4];
#pragma unroll
    for (int nt = 0; nt < 8; nt++)
#pragma unroll
        for (int i = 0; i < 4; i++) c2[nt][i] = 0.f;

    for (int kt = 0; kt <= qt; kt++) {
        __syncthreads();
        const float* kb = kbase + (size_t)kt * 64 * 128;
        const float* vb = vbase + (size_t)kt * 64 * 128;
        for (int L = tid; L < 2048; L += 256) {
            int row = L >> 5, c4 = (L & 31) << 2;
            float4 kv = *(const float4*)(kb + row * 128 + c4);
            Ks[(c4 + 0) * 68 + row] = kv.x;
            Ks[(c4 + 1) * 68 + row] = kv.y;
            Ks[(c4 + 2) * 68 + row] = kv.z;
            Ks[(c4 + 3) * 68 + row] = kv.w;
            *(float4*)(Vs + row * 132 + c4) = *(const float4*)(vb + row * 128 + c4);
        }
        __syncthreads();

        // ---- S = Q K^T, tf32x3 ----
        float cs[4][4];
#pragma unroll
        for (int nt = 0; nt < 4; nt++)
#pragma unroll
            for (int i = 0; i < 4; i++) cs[nt][i] = 0.f;

#pragma unroll 4
        for (int kb8 = 0; kb8 < 128; kb8 += 8) {
            unsigned ah[4], al[4];
            {
                float v0 = Qs[(wmS + gg    ) * 132 + kb8 + tg    ];
                float v1 = Qs[(wmS + gg + 8) * 132 + kb8 + tg    ];
                float v2 = Qs[(wmS + gg    ) * 132 + kb8 + tg + 4];
                float v3 = Qs[(wmS + gg + 8) * 132 + kb8 + tg + 4];
                ah[0] = f2tf(v0); al[0] = f2tf(v0 - __uint_as_float(ah[0]));
                ah[1] = f2tf(v1); al[1] = f2tf(v1 - __uint_as_float(ah[1]));
                ah[2] = f2tf(v2); al[2] = f2tf(v2 - __uint_as_float(ah[2]));
                ah[3] = f2tf(v3); al[3] = f2tf(v3 - __uint_as_float(ah[3]));
            }
#pragma unroll
            for (int nt = 0; nt < 4; nt++) {
                int cn = wnS + nt * 8 + gg;
                float w0 = Ks[(kb8 + tg    ) * 68 + cn];
                float w1 = Ks[(kb8 + tg + 4) * 68 + cn];
                unsigned bh0 = f2tf(w0), bh1 = f2tf(w1);
                unsigned bl0 = f2tf(w0 - __uint_as_float(bh0));
                unsigned bl1 = f2tf(w1 - __uint_as_float(bh1));
                MMA_TF32(cs[nt], ah, bh0, bh1);
                MMA_TF32(cs[nt], al, bh0, bh1);
                MMA_TF32(cs[nt], ah, bl0, bl1);
            }
        }
        // write scores with causal mask + scale
        {
            int qi0 = qt * 64 + wmS + gg;
            int qi1 = qi0 + 8;
#pragma unroll
            for (int nt = 0; nt < 4; nt++) {
                int col = wnS + nt * 8 + tg * 2;
                int kj = kt * 64 + col;
                Ss[(wmS + gg    ) * 68 + col    ] = (kj     <= qi0) ? cs[nt][0] * SC : -1e30f;
                Ss[(wmS + gg    ) * 68 + col + 1] = (kj + 1 <= qi0) ? cs[nt][1] * SC : -1e30f;
                Ss[(wmS + gg + 8) * 68 + col    ] = (kj     <= qi1) ? cs[nt][2] * SC : -1e30f;
                Ss[(wmS + gg + 8) * 68 + col + 1] = (kj + 1 <= qi1) ? cs[nt][3] * SC : -1e30f;
            }
        }
        __syncthreads();

        // ---- online softmax, 4 threads per row ----
        {
            int r = tid >> 2, part = tid & 3, base = part * 16;
            float mold = rowm[r];
            float tmax = mold;
#pragma unroll
            for (int j = 0; j < 16; j++) tmax = fmaxf(tmax, Ss[r * 68 + base + j]);
            tmax = fmaxf(tmax, __shfl_xor_sync(0xFFFFFFFFu, tmax, 1));
            tmax = fmaxf(tmax, __shfl_xor_sync(0xFFFFFFFFu, tmax, 2));
            float sum = 0.f;
#pragma unroll
            for (int j = 0; j < 16; j++) {
                float p = __expf(Ss[r * 68 + base + j] - tmax);
                Ss[r * 68 + base + j] = p;
                sum += p;
            }
            sum += __shfl_xor_sync(0xFFFFFFFFu, sum, 1);
            sum += __shfl_xor_sync(0xFFFFFFFFu, sum, 2);
            if (part == 0) {
                float sc = __expf(mold - tmax);
                rowsc[r] = sc;
                rowl[r] = rowl[r] * sc + sum;
                rowm[r] = tmax;
            }
        }
        __syncthreads();

        // ---- rescale accumulators + PV (tf32x3) ----
        {
            float s0 = rowsc[wmS + gg], s1 = rowsc[wmS + gg + 8];
#pragma unroll
            for (int nt = 0; nt < 8; nt++) {
                c2[nt][0] *= s0; c2[nt][1] *= s0;
                c2[nt][2] *= s1; c2[nt][3] *= s1;
            }
        }
#pragma unroll
        for (int kb8 = 0; kb8 < 64; kb8 += 8) {
            unsigned ah[4], al[4];
            {
                float v0 = Ss[(wmS + gg    ) * 68 + kb8 + tg    ];
                float v1 = Ss[(wmS + gg + 8) * 68 + kb8 + tg    ];
                float v2 = Ss[(wmS + gg    ) * 68 + kb8 + tg + 4];
                float v3 = Ss[(wmS + gg + 8) * 68 + kb8 + tg + 4];
                ah[0] = f2tf(v0); al[0] = f2tf(v0 - __uint_as_float(ah[0]));
                ah[1] = f2tf(v1); al[1] = f2tf(v1 - __uint_as_float(ah[1]));
                ah[2] = f2tf(v2); al[2] = f2tf(v2 - __uint_as_float(ah[2]));
                ah[3] = f2tf(v3); al[3] = f2tf(v3 - __uint_as_float(ah[3]));
            }
#pragma unroll
            for (int nt = 0; nt < 8; nt++) {
                int cn = wnP + nt * 8 + gg;
                float w0 = Vs[(kb8 + tg    ) * 132 + cn];
                float w1 = Vs[(kb8 + tg + 4) * 132 + cn];
                unsigned bh0 = f2tf(w0), bh1 = f2tf(w1);
                unsigned bl0 = f2tf(w0 - __uint_as_float(bh0));
                unsigned bl1 = f2tf(w1 - __uint_as_float(bh1));
                MMA_TF32(c2[nt], ah, bh0, bh1);
                MMA_TF32(c2[nt], al, bh0, bh1);
                MMA_TF32(c2[nt], ah, bl0, bl1);
            }
        }
    }
    __syncthreads();

    // ---- epilogue ----
    {
        float inv0 = 1.f / rowl[wmS + gg];
        float inv1 = 1.f / rowl[wmS + gg + 8];
        int row0 = qt * 64 + wmS + gg;
#pragma unroll
        for (int nt = 0; nt < 8; nt++) {
            int col = wnP + nt * 8 + tg * 2;
            float* op0 = gy + ((size_t)b * T_ + row0) * C_ + h * HD_ + col;
            float* op1 = gy + ((size_t)b * T_ + row0 + 8) * C_ + h * HD_ + col;
            float2 o0 = {c2[nt][0] * inv0, c2[nt][1] * inv0};
            float2 o1 = {c2[nt][2] * inv1, c2[nt][3] * inv1};
            *(float2*)op0 = o0;
            *(float2*)op1 = o1;
        }
    }
}

// ---------------- launch ----------------
extern "C" void kernel_launch(void* const* d_in, const int* in_sizes, int n_in,
                              void* d_out, int out_size) {
    const float* x    = (const float*)d_in[0];
    const float* cosp = (const float*)d_in[1];
    const float* sinp = (const float*)d_in[2];
    const float* Wq   = (const float*)d_in[3];
    const float* bq   = (const float*)d_in[4];
    const float* Wk   = (const float*)d_in[5];
    const float* bk   = (const float*)d_in[6];
    const float* Wv   = (const float*)d_in[7];
    const float* bv   = (const float*)d_in[8];
    const float* Wo   = (const float*)d_in[9];
    float* out = (float*)d_out;

    float *qt, *ktp, *vtp, *q, *k, *v, *y;
    cudaGetSymbolAddress((void**)&qt,  g_qt);
    cudaGetSymbolAddress((void**)&ktp, g_kt);
    cudaGetSymbolAddress((void**)&vtp, g_vt);
    cudaGetSymbolAddress((void**)&q,   g_q);
    cudaGetSymbolAddress((void**)&k,   g_k);
    cudaGetSymbolAddress((void**)&v,   g_v);
    cudaGetSymbolAddress((void**)&y,   g_y);

    dim3 blk(256);

    gemm_tf32x3_kernel<<<dim3(2048/128, BT_/128), blk>>>(x, Wq, bq, qt,  BT_, 2048, C_);
    gemm_tf32x3_kernel<<<dim3(512/128,  BT_/128), blk>>>(x, Wk, bk, ktp, BT_, 512,  C_);
    gemm_tf32x3_kernel<<<dim3(512/128,  BT_/128), blk>>>(x, Wv, bv, vtp, BT_, 512,  C_);

    {
        int nq = B_ * T_ * H_ * 64;
        rope_transpose_kernel<<<(nq + 255)/256, 256>>>(qt, cosp, sinp, q, H_);
        int nk = B_ * T_ * HK_ * 64;
        rope_transpose_kernel<<<(nk + 255)/256, 256>>>(ktp, cosp, sinp, k, HK_);
        int nv = B_ * T_ * HK_ * HD_;
        transpose_v_kernel<<<(nv + 255)/256, 256>>>(vtp, v);
    }

    cudaFuncSetAttribute(attn_mma_kernel, cudaFuncAttributeMaxDynamicSharedMemorySize, AT_BYTES);
    attn_mma_kernel<<<dim3(T_/64, H_, B_), blk, AT_BYTES>>>(q, k, v, y);

    gemm_tf32x3_kernel<<<dim3(2048/128, BT_/128), blk>>>(y, Wo, nullptr, out, BT_, C_, C_);
}

// round 11
// speedup vs baseline: 2.3842x; 1.6783x over previous
#include <cuda_runtime.h>
#include <cuda_bf16.h>
#include <cstddef>

#define B_  2
#define T_  2048
#define C_  2048
#define H_  16
#define HK_ 4
#define HD_ 128
#define BT_ (B_*T_)

__device__ float g_qt[(size_t)BT_ * 2048];
__device__ float g_kt[(size_t)BT_ * 512];
__device__ float g_vt[(size_t)BT_ * 512];
__device__ float g_q [(size_t)B_*H_ *T_*HD_];
__device__ float g_k [(size_t)B_*HK_*T_*HD_];
__device__ float g_v [(size_t)B_*HK_*T_*HD_];
__device__ float g_y [(size_t)BT_ * C_];

#define MMA_BF16(Cacc, Af, b0, b1)                                                 \
    asm volatile("mma.sync.aligned.m16n8k16.row.col.f32.bf16.bf16.f32 "            \
        "{%0,%1,%2,%3}, {%4,%5,%6,%7}, {%8,%9}, {%0,%1,%2,%3};"                    \
        : "+f"(Cacc[0]), "+f"(Cacc[1]), "+f"(Cacc[2]), "+f"(Cacc[3])               \
        : "r"(Af[0]), "r"(Af[1]), "r"(Af[2]), "r"(Af[3]), "r"(b0), "r"(b1))

// split two floats into packed bf16x2 hi + lo (elem0 = low half)
__device__ __forceinline__ void split2(float a, float b, unsigned& h, unsigned& l) {
    __nv_bfloat162 hb = __floats2bfloat162_rn(a, b);
    float ha = __bfloat162float(hb.x), hbv = __bfloat162float(hb.y);
    __nv_bfloat162 lb = __floats2bfloat162_rn(a - ha, b - hbv);
    h = *reinterpret_cast<unsigned*>(&hb);
    l = *reinterpret_cast<unsigned*>(&lb);
}

// ---------------- 3xBF16 tensor-core GEMM: C = A[M,K] @ W[K,N] (+bias) ----------------
// BM=BN=128, BK=16, 256 threads (8 warps: 4M x 2N), m16n8k16 bf16 mma.
__global__ __launch_bounds__(256) void gemm_bf16x3_kernel(
    const float* __restrict__ A, const float* __restrict__ W,
    const float* __restrict__ bias, float* __restrict__ Cout,
    int M, int N, int K)
{
    __shared__ unsigned Ah[128][12];   // [m][kpair] (8 used, stride 12 conflict-free)
    __shared__ unsigned Al[128][12];
    __shared__ unsigned Wh[8][136];    // [kpair][n] (stride 136 conflict-free)
    __shared__ unsigned Wl[8][136];

    const int tid  = threadIdx.x;
    const int bm   = blockIdx.y * 128;
    const int bn   = blockIdx.x * 128;
    const int lane = tid & 31, warp = tid >> 5;
    const int wm   = (warp & 3) * 32;
    const int wn   = (warp >> 2) * 64;
    const int g    = lane >> 2, tg = lane & 3;

    const int ar0 = tid >> 2, ac4 = (tid & 3) * 4;   // A rows ar0, ar0+64; k off ac4
    const int wk0 = tid >> 5, wn4 = (tid & 31) * 4;  // W pair-row wk0; cols wn4..+3

    float4 aR[2], wR[2];
    float c[2][8][4];
#pragma unroll
    for (int mt = 0; mt < 2; mt++)
#pragma unroll
        for (int nt = 0; nt < 8; nt++)
#pragma unroll
            for (int i = 0; i < 4; i++) c[mt][nt][i] = 0.f;

    auto loadG = [&](int k0) {
        aR[0] = *(const float4*)(A + (size_t)(bm + ar0)      * K + k0 + ac4);
        aR[1] = *(const float4*)(A + (size_t)(bm + ar0 + 64) * K + k0 + ac4);
        wR[0] = *(const float4*)(W + (size_t)(k0 + 2*wk0)     * N + bn + wn4);
        wR[1] = *(const float4*)(W + (size_t)(k0 + 2*wk0 + 1) * N + bn + wn4);
    };

    auto storeS = [&]() {
#pragma unroll
        for (int i = 0; i < 2; i++) {
            int r = ar0 + i * 64;
            unsigned h0, l0, h1, l1;
            split2(((float*)&aR[i])[0], ((float*)&aR[i])[1], h0, l0);
            split2(((float*)&aR[i])[2], ((float*)&aR[i])[3], h1, l1);
            Ah[r][ac4/2]     = h0;  Al[r][ac4/2]     = l0;
            Ah[r][ac4/2 + 1] = h1;  Al[r][ac4/2 + 1] = l1;
        }
#pragma unroll
        for (int j = 0; j < 4; j++) {
            unsigned h, l;
            split2(((float*)&wR[0])[j], ((float*)&wR[1])[j], h, l);
            Wh[wk0][wn4 + j] = h;
            Wl[wk0][wn4 + j] = l;
        }
    };

    auto computeTile = [&]() {
        unsigned ah[2][4], al[2][4];
#pragma unroll
        for (int mt = 0; mt < 2; mt++) {
            int r = wm + mt * 16;
            ah[mt][0] = Ah[r + g    ][tg];
            ah[mt][1] = Ah[r + g + 8][tg];
            ah[mt][2] = Ah[r + g    ][tg + 4];
            ah[mt][3] = Ah[r + g + 8][tg + 4];
            al[mt][0] = Al[r + g    ][tg];
            al[mt][1] = Al[r + g + 8][tg];
            al[mt][2] = Al[r + g    ][tg + 4];
            al[mt][3] = Al[r + g + 8][tg + 4];
        }
#pragma unroll
        for (int nt = 0; nt < 8; nt++) {
            int cn = wn + nt * 8 + g;
            unsigned bh0 = Wh[tg    ][cn];
            unsigned bh1 = Wh[tg + 4][cn];
            unsigned bl0 = Wl[tg    ][cn];
            unsigned bl1 = Wl[tg + 4][cn];
#pragma unroll
            for (int mt = 0; mt < 2; mt++) {
                MMA_BF16(c[mt][nt], ah[mt], bh0, bh1);
                MMA_BF16(c[mt][nt], al[mt], bh0, bh1);
                MMA_BF16(c[mt][nt], ah[mt], bl0, bl1);
            }
        }
    };

    loadG(0);
    storeS();
    __syncthreads();
    for (int k0 = 16; k0 < K; k0 += 16) {
        loadG(k0);
        computeTile();
        __syncthreads();
        storeS();
        __syncthreads();
    }
    computeTile();

#pragma unroll
    for (int mt = 0; mt < 2; mt++) {
        int r0 = bm + wm + mt * 16 + g;
#pragma unroll
        for (int nt = 0; nt < 8; nt++) {
            int col = bn + wn + nt * 8 + tg * 2;
            float b0 = 0.f, b1 = 0.f;
            if (bias) { b0 = bias[col]; b1 = bias[col + 1]; }
            float2 v0 = {c[mt][nt][0] + b0, c[mt][nt][1] + b1};
            float2 v1 = {c[mt][nt][2] + b0, c[mt][nt][3] + b1};
            *(float2*)(Cout + (size_t)r0 * N + col)       = v0;
            *(float2*)(Cout + (size_t)(r0 + 8) * N + col) = v1;
        }
    }
}

// ---------------- RoPE + transposes (unchanged) ----------------
__global__ void rope_transpose_kernel(const float* __restrict__ in, const float* __restrict__ cosp,
                                      const float* __restrict__ sinp, float* __restrict__ outp, int Hn) {
    int idx = blockIdx.x * blockDim.x + threadIdx.x;
    int total = B_ * T_ * Hn * 64;
    if (idx >= total) return;
    int d = idx & 63;
    int h = (idx >> 6) % Hn;
    int t = (idx / (64 * Hn)) % T_;
    int b = idx / (64 * Hn * T_);
    size_t ibase = ((size_t)(b * T_ + t) * Hn + h) * HD_;
    float x1 = in[ibase + d];
    float x2 = in[ibase + d + 64];
    size_t cbase = (size_t)(b * T_ + t) * HD_;
    float c1 = cosp[cbase + d],      s1 = sinp[cbase + d];
    float c2 = cosp[cbase + d + 64], s2 = sinp[cbase + d + 64];
    size_t obase = (((size_t)b * Hn + h) * T_ + t) * HD_;
    outp[obase + d]      = x1 * c1 - x2 * s1;
    outp[obase + d + 64] = x2 * c2 + x1 * s2;
}

__global__ void transpose_v_kernel(const float* __restrict__ in, float* __restrict__ outp) {
    int idx = blockIdx.x * blockDim.x + threadIdx.x;
    int total = B_ * T_ * HK_ * HD_;
    if (idx >= total) return;
    int d  = idx & 127;
    int hk = (idx >> 7) & 3;
    int t  = (idx >> 9) % T_;
    int b  = idx / (512 * T_);
    outp[(((size_t)b * HK_ + hk) * T_ + t) * HD_ + d] =
        in[((size_t)(b * T_ + t) * HK_ + hk) * HD_ + d];
}

// ---------------- flash attention on bf16x3 mma ----------------
#define AT_QS   0
#define AT_KS   (64*132)
#define AT_VS   (AT_KS + 128*68)
#define AT_SS   (AT_VS + 64*132)
#define AT_RM   (AT_SS + 64*68)
#define AT_FLOATS (AT_RM + 3*64)
#define AT_BYTES  (AT_FLOATS * 4)

__global__ __launch_bounds__(256) void attn_mma_kernel(
    const float* __restrict__ gq, const float* __restrict__ gk,
    const float* __restrict__ gv, float* __restrict__ gy)
{
    extern __shared__ float sm[];
    float* Qs   = sm + AT_QS;    // [64][132] row-major
    float* Ks   = sm + AT_KS;    // [128][68] K^T: [k][key]
    float* Vs   = sm + AT_VS;    // [64][132] [key][d]
    float* Ss   = sm + AT_SS;    // [64][68]
    float* rowm = sm + AT_RM;
    float* rowl = rowm + 64;
    float* rowsc = rowl + 64;

    const int qt = blockIdx.x, h = blockIdx.y, b = blockIdx.z;
    const int grp = h >> 2;
    const int tid = threadIdx.x, lane = tid & 31, warp = tid >> 5;
    const int gg = lane >> 2, tg = lane & 3;
    const int wmS = (warp & 3) * 16, wnS = (warp >> 2) * 32;
    const int wnP = (warp >> 2) * 64;
    const float SC = 0.08838834764831845f;

    const float* qbase = gq + (((size_t)b * H_  + h)   * T_ + (size_t)qt * 64) * HD_;
    const float* kbase = gk + ((size_t)b * HK_ + grp) * T_ * HD_;
    const float* vbase = gv + ((size_t)b * HK_ + grp) * T_ * HD_;

    for (int L = tid; L < 2048; L += 256) {
        int row = L >> 5, c4 = (L & 31) << 2;
        *(float4*)(Qs + row * 132 + c4) = *(const float4*)(qbase + row * 128 + c4);
    }
    if (tid < 64) { rowm[tid] = -1e30f; rowl[tid] = 0.f; }

    float c2[8][4];
#pragma unroll
    for (int nt = 0; nt < 8; nt++)
#pragma unroll
        for (int i = 0; i < 4; i++) c2[nt][i] = 0.f;

    for (int kt = 0; kt <= qt; kt++) {
        __syncthreads();
        const float* kb = kbase + (size_t)kt * 64 * 128;
        const float* vb = vbase + (size_t)kt * 64 * 128;
        for (int L = tid; L < 2048; L += 256) {
            int row = L >> 5, c4 = (L & 31) << 2;
            float4 kv = *(const float4*)(kb + row * 128 + c4);
            Ks[(c4 + 0) * 68 + row] = kv.x;
            Ks[(c4 + 1) * 68 + row] = kv.y;
            Ks[(c4 + 2) * 68 + row] = kv.z;
            Ks[(c4 + 3) * 68 + row] = kv.w;
            *(float4*)(Vs + row * 132 + c4) = *(const float4*)(vb + row * 128 + c4);
        }
        __syncthreads();

        // ---- S = Q K^T, bf16x3 m16n8k16 ----
        float cs[4][4];
#pragma unroll
        for (int nt = 0; nt < 4; nt++)
#pragma unroll
            for (int i = 0; i < 4; i++) cs[nt][i] = 0.f;

        const float* qr0 = Qs + (wmS + gg) * 132;
        const float* qr1 = qr0 + 8 * 132;
#pragma unroll
        for (int kb16 = 0; kb16 < 128; kb16 += 16) {
            int ki = kb16 + 2 * tg;
            unsigned ah[4], al[4];
            split2(qr0[ki],     qr0[ki + 1], ah[0], al[0]);
            split2(qr1[ki],     qr1[ki + 1], ah[1], al[1]);
            split2(qr0[ki + 8], qr0[ki + 9], ah[2], al[2]);
            split2(qr1[ki + 8], qr1[ki + 9], ah[3], al[3]);
#pragma unroll
            for (int nt = 0; nt < 4; nt++) {
                int cn = wnS + nt * 8 + gg;
                unsigned bh0, bl0, bh1, bl1;
                split2(Ks[ki * 68 + cn],       Ks[(ki + 1) * 68 + cn], bh0, bl0);
                split2(Ks[(ki + 8) * 68 + cn], Ks[(ki + 9) * 68 + cn], bh1, bl1);
                MMA_BF16(cs[nt], ah, bh0, bh1);
                MMA_BF16(cs[nt], al, bh0, bh1);
                MMA_BF16(cs[nt], ah, bl0, bl1);
            }
        }
        {
            int qi0 = qt * 64 + wmS + gg;
            int qi1 = qi0 + 8;
#pragma unroll
            for (int nt = 0; nt < 4; nt++) {
                int col = wnS + nt * 8 + tg * 2;
                int kj = kt * 64 + col;
                Ss[(wmS + gg    ) * 68 + col    ] = (kj     <= qi0) ? cs[nt][0] * SC : -1e30f;
                Ss[(wmS + gg    ) * 68 + col + 1] = (kj + 1 <= qi0) ? cs[nt][1] * SC : -1e30f;
                Ss[(wmS + gg + 8) * 68 + col    ] = (kj     <= qi1) ? cs[nt][2] * SC : -1e30f;
                Ss[(wmS + gg + 8) * 68 + col + 1] = (kj + 1 <= qi1) ? cs[nt][3] * SC : -1e30f;
            }
        }
        __syncthreads();

        // ---- online softmax, 4 threads per row ----
        {
            int r = tid >> 2, part = tid & 3, base = part * 16;
            float mold = rowm[r];
            float tmax = mold;
#pragma unroll
            for (int j = 0; j < 16; j++) tmax = fmaxf(tmax, Ss[r * 68 + base + j]);
            tmax = fmaxf(tmax, __shfl_xor_sync(0xFFFFFFFFu, tmax, 1));
            tmax = fmaxf(tmax, __shfl_xor_sync(0xFFFFFFFFu, tmax, 2));
            float sum = 0.f;
#pragma unroll
            for (int j = 0; j < 16; j++) {
                float p = __expf(Ss[r * 68 + base + j] - tmax);
                Ss[r * 68 + base + j] = p;
                sum += p;
            }
            sum += __shfl_xor_sync(0xFFFFFFFFu, sum, 1);
            sum += __shfl_xor_sync(0xFFFFFFFFu, sum, 2);
            if (part == 0) {
                float sc = __expf(mold - tmax);
                rowsc[r] = sc;
                rowl[r] = rowl[r] * sc + sum;
                rowm[r] = tmax;
            }
        }
        __syncthreads();

        // ---- rescale + PV (bf16x3) ----
        {
            float s0 = rowsc[wmS + gg], s1 = rowsc[wmS + gg + 8];
#pragma unroll
            for (int nt = 0; nt < 8; nt++) {
                c2[nt][0] *= s0; c2[nt][1] *= s0;
                c2[nt][2] *= s1; c2[nt][3] *= s1;
            }
        }
        const float* pr0 = Ss + (wmS + gg) * 68;
        const float* pr1 = pr0 + 8 * 68;
#pragma unroll
        for (int kb16 = 0; kb16 < 64; kb16 += 16) {
            int ki = kb16 + 2 * tg;
            unsigned ah[4], al[4];
            split2(pr0[ki],     pr0[ki + 1], ah[0], al[0]);
            split2(pr1[ki],     pr1[ki + 1], ah[1], al[1]);
            split2(pr0[ki + 8], pr0[ki + 9], ah[2], al[2]);
            split2(pr1[ki + 8], pr1[ki + 9], ah[3], al[3]);
#pragma unroll
            for (int nt = 0; nt < 8; nt++) {
                int cn = wnP + nt * 8 + gg;
                unsigned bh0, bl0, bh1, bl1;
                split2(Vs[ki * 132 + cn],       Vs[(ki + 1) * 132 + cn], bh0, bl0);
                split2(Vs[(ki + 8) * 132 + cn], Vs[(ki + 9) * 132 + cn], bh1, bl1);
                MMA_BF16(c2[nt], ah, bh0, bh1);
                MMA_BF16(c2[nt], al, bh0, bh1);
                MMA_BF16(c2[nt], ah, bl0, bl1);
            }
        }
    }
    __syncthreads();

    {
        float inv0 = 1.f / rowl[wmS + gg];
        float inv1 = 1.f / rowl[wmS + gg + 8];
        int row0 = qt * 64 + wmS + gg;
#pragma unroll
        for (int nt = 0; nt < 8; nt++) {
            int col = wnP + nt * 8 + tg * 2;
            float* op0 = gy + ((size_t)b * T_ + row0) * C_ + h * HD_ + col;
            float* op1 = gy + ((size_t)b * T_ + row0 + 8) * C_ + h * HD_ + col;
            float2 o0 = {c2[nt][0] * inv0, c2[nt][1] * inv0};
            float2 o1 = {c2[nt][2] * inv1, c2[nt][3] * inv1};
            *(float2*)op0 = o0;
            *(float2*)op1 = o1;
        }
    }
}

// ---------------- launch ----------------
extern "C" void kernel_launch(void* const* d_in, const int* in_sizes, int n_in,
                              void* d_out, int out_size) {
    const float* x    = (const float*)d_in[0];
    const float* cosp = (const float*)d_in[1];
    const float* sinp = (const float*)d_in[2];
    const float* Wq   = (const float*)d_in[3];
    const float* bq   = (const float*)d_in[4];
    const float* Wk   = (const float*)d_in[5];
    const float* bk   = (const float*)d_in[6];
    const float* Wv   = (const float*)d_in[7];
    const float* bv   = (const float*)d_in[8];
    const float* Wo   = (const float*)d_in[9];
    float* out = (float*)d_out;

    float *qt, *ktp, *vtp, *q, *k, *v, *y;
    cudaGetSymbolAddress((void**)&qt,  g_qt);
    cudaGetSymbolAddress((void**)&ktp, g_kt);
    cudaGetSymbolAddress((void**)&vtp, g_vt);
    cudaGetSymbolAddress((void**)&q,   g_q);
    cudaGetSymbolAddress((void**)&k,   g_k);
    cudaGetSymbolAddress((void**)&v,   g_v);
    cudaGetSymbolAddress((void**)&y,   g_y);

    dim3 blk(256);

    gemm_bf16x3_kernel<<<dim3(2048/128, BT_/128), blk>>>(x, Wq, bq, qt,  BT_, 2048, C_);
    gemm_bf16x3_kernel<<<dim3(512/128,  BT_/128), blk>>>(x, Wk, bk, ktp, BT_, 512,  C_);
    gemm_bf16x3_kernel<<<dim3(512/128,  BT_/128), blk>>>(x, Wv, bv, vtp, BT_, 512,  C_);

    {
        int nq = B_ * T_ * H_ * 64;
        rope_transpose_kernel<<<(nq + 255)/256, 256>>>(qt, cosp, sinp, q, H_);
        int nk = B_ * T_ * HK_ * 64;
        rope_transpose_kernel<<<(nk + 255)/256, 256>>>(ktp, cosp, sinp, k, HK_);
        int nv = B_ * T_ * HK_ * HD_;
        transpose_v_kernel<<<(nv + 255)/256, 256>>>(vtp, v);
    }

    cudaFuncSetAttribute(attn_mma_kernel, cudaFuncAttributeMaxDynamicSharedMemorySize, AT_BYTES);
    attn_mma_kernel<<<dim3(T_/64, H_, B_), blk, AT_BYTES>>>(q, k, v, y);

    gemm_bf16x3_kernel<<<dim3(2048/128, BT_/128), blk>>>(y, Wo, nullptr, out, BT_, C_, C_);
}

// round 12
// speedup vs baseline: 2.9129x; 1.2217x over previous
#include <cuda_runtime.h>
#include <cuda_bf16.h>
#include <cstddef>

#define B_  2
#define T_  2048
#define C_  2048
#define H_  16
#define HK_ 4
#define HD_ 128
#define BT_ (B_*T_)

// fp32 intermediates
__device__ float g_qt[(size_t)BT_ * 2048];
__device__ float g_kt[(size_t)BT_ * 512];
__device__ float g_vt[(size_t)BT_ * 512];
__device__ float g_y [(size_t)BT_ * C_];
// packed bf16 hi/lo operands
__device__ unsigned g_xph[(size_t)BT_ * 1024], g_xpl[(size_t)BT_ * 1024];
__device__ unsigned g_yph[(size_t)BT_ * 1024], g_ypl[(size_t)BT_ * 1024];
__device__ unsigned g_wqph[(size_t)1024 * 2048], g_wqpl[(size_t)1024 * 2048];
__device__ unsigned g_wkph[(size_t)1024 * 512],  g_wkpl[(size_t)1024 * 512];
__device__ unsigned g_wvph[(size_t)1024 * 512],  g_wvpl[(size_t)1024 * 512];
__device__ unsigned g_woph[(size_t)1024 * 2048], g_wopl[(size_t)1024 * 2048];
__device__ unsigned g_qph[(size_t)B_*H_ *T_*64], g_qpl[(size_t)B_*H_ *T_*64];
__device__ unsigned g_kph[(size_t)B_*HK_*T_*64], g_kpl[(size_t)B_*HK_*T_*64];
__device__ unsigned g_vph[(size_t)B_*HK_*(T_/2)*128], g_vpl[(size_t)B_*HK_*(T_/2)*128];

#define MMA_BF16(Cacc, Af, b0, b1)                                                 \
    asm volatile("mma.sync.aligned.m16n8k16.row.col.f32.bf16.bf16.f32 "            \
        "{%0,%1,%2,%3}, {%4,%5,%6,%7}, {%8,%9}, {%0,%1,%2,%3};"                    \
        : "+f"(Cacc[0]), "+f"(Cacc[1]), "+f"(Cacc[2]), "+f"(Cacc[3])               \
        : "r"(Af[0]), "r"(Af[1]), "r"(Af[2]), "r"(Af[3]), "r"(b0), "r"(b1))

__device__ __forceinline__ void split2(float a, float b, unsigned& h, unsigned& l) {
    __nv_bfloat162 hb = __floats2bfloat162_rn(a, b);
    float ha = __bfloat162float(hb.x), hbv = __bfloat162float(hb.y);
    __nv_bfloat162 lb = __floats2bfloat162_rn(a - ha, b - hbv);
    h = *reinterpret_cast<unsigned*>(&hb);
    l = *reinterpret_cast<unsigned*>(&lb);
}

// ---------------- prep: row-pack [M][K] f32 -> [M][K/2] u32 hi/lo ----------------
__global__ void split_pack_rows(const float* __restrict__ in, unsigned* __restrict__ oh,
                                unsigned* __restrict__ ol, int n8) {
    int i = blockIdx.x * blockDim.x + threadIdx.x;
    if (i >= n8) return;
    float4 a = ((const float4*)in)[2*i], b = ((const float4*)in)[2*i + 1];
    uint4 h, l;
    split2(a.x, a.y, h.x, l.x);  split2(a.z, a.w, h.y, l.y);
    split2(b.x, b.y, h.z, l.z);  split2(b.z, b.w, h.w, l.w);
    ((uint4*)oh)[i] = h;  ((uint4*)ol)[i] = l;
}

// ---------------- prep: pack W [K][N] -> [K/2][N] u32 (pairs along K) ----------------
__global__ void pack_w(const float* __restrict__ W, unsigned* __restrict__ oh,
                       unsigned* __restrict__ ol, int K, int N) {
    int i = blockIdx.x * blockDim.x + threadIdx.x;
    int n4q = N >> 2;
    if (i >= (K/2) * n4q) return;
    int kp = i / n4q, n4 = (i % n4q) * 4;
    float4 r0 = *(const float4*)(W + (size_t)(2*kp)     * N + n4);
    float4 r1 = *(const float4*)(W + (size_t)(2*kp + 1) * N + n4);
    uint4 h, l;
    split2(r0.x, r1.x, h.x, l.x);  split2(r0.y, r1.y, h.y, l.y);
    split2(r0.z, r1.z, h.z, l.z);  split2(r0.w, r1.w, h.w, l.w);
    *(uint4*)(oh + (size_t)kp * N + n4) = h;
    *(uint4*)(ol + (size_t)kp * N + n4) = l;
}

// ---------------- 3xBF16 GEMM on pre-packed operands ----------------
__global__ __launch_bounds__(256) void gemm_pk_kernel(
    const unsigned* __restrict__ Aph, const unsigned* __restrict__ Apl,
    const unsigned* __restrict__ Wph, const unsigned* __restrict__ Wpl,
    const float* __restrict__ bias, float* __restrict__ Cout,
    int M, int N, int Kp)
{
    __shared__ unsigned Ah[128][12], Al[128][12];
    __shared__ unsigned Wh[8][136],  Wl[8][136];

    const int tid  = threadIdx.x;
    const int bm   = blockIdx.y * 128, bn = blockIdx.x * 128;
    const int lane = tid & 31, warp = tid >> 5;
    const int wm   = (warp & 3) * 32, wn = (warp >> 2) * 64;
    const int g    = lane >> 2, tg = lane & 3;

    const int arow = tid >> 1, ahalf = (tid & 1) * 4;
    const int wkp  = tid >> 5, wn4   = (tid & 31) * 4;

    uint4 aH, aL, wH, wL;
    float c[2][8][4];
#pragma unroll
    for (int mt = 0; mt < 2; mt++)
#pragma unroll
        for (int nt = 0; nt < 8; nt++)
#pragma unroll
            for (int i = 0; i < 4; i++) c[mt][nt][i] = 0.f;

    auto loadG = [&](int kp0) {
        aH = *(const uint4*)(Aph + (size_t)(bm + arow) * Kp + kp0 + ahalf);
        aL = *(const uint4*)(Apl + (size_t)(bm + arow) * Kp + kp0 + ahalf);
        wH = *(const uint4*)(Wph + (size_t)(kp0 + wkp) * N + bn + wn4);
        wL = *(const uint4*)(Wpl + (size_t)(kp0 + wkp) * N + bn + wn4);
    };
    auto storeS = [&]() {
        *(uint4*)&Ah[arow][ahalf] = aH;
        *(uint4*)&Al[arow][ahalf] = aL;
        *(uint4*)&Wh[wkp][wn4]    = wH;
        *(uint4*)&Wl[wkp][wn4]    = wL;
    };
    auto computeTile = [&]() {
        unsigned ah[2][4], al[2][4];
#pragma unroll
        for (int mt = 0; mt < 2; mt++) {
            int r = wm + mt * 16;
            ah[mt][0] = Ah[r + g    ][tg];
            ah[mt][1] = Ah[r + g + 8][tg];
            ah[mt][2] = Ah[r + g    ][tg + 4];
            ah[mt][3] = Ah[r + g + 8][tg + 4];
            al[mt][0] = Al[r + g    ][tg];
            al[mt][1] = Al[r + g + 8][tg];
            al[mt][2] = Al[r + g    ][tg + 4];
            al[mt][3] = Al[r + g + 8][tg + 4];
        }
#pragma unroll
        for (int nt = 0; nt < 8; nt++) {
            int cn = wn + nt * 8 + g;
            unsigned bh0 = Wh[tg][cn], bh1 = Wh[tg + 4][cn];
            unsigned bl0 = Wl[tg][cn], bl1 = Wl[tg + 4][cn];
#pragma unroll
            for (int mt = 0; mt < 2; mt++) {
                MMA_BF16(c[mt][nt], ah[mt], bh0, bh1);
                MMA_BF16(c[mt][nt], al[mt], bh0, bh1);
                MMA_BF16(c[mt][nt], ah[mt], bl0, bl1);
            }
        }
    };

    loadG(0);
    storeS();
    __syncthreads();
    for (int kp0 = 8; kp0 < Kp; kp0 += 8) {
        loadG(kp0);
        computeTile();
        __syncthreads();
        storeS();
        __syncthreads();
    }
    computeTile();

#pragma unroll
    for (int mt = 0; mt < 2; mt++) {
        int r0 = bm + wm + mt * 16 + g;
#pragma unroll
        for (int nt = 0; nt < 8; nt++) {
            int col = bn + wn + nt * 8 + tg * 2;
            float b0 = 0.f, b1 = 0.f;
            if (bias) { b0 = bias[col]; b1 = bias[col + 1]; }
            float2 v0 = {c[mt][nt][0] + b0, c[mt][nt][1] + b1};
            float2 v1 = {c[mt][nt][2] + b0, c[mt][nt][3] + b1};
            *(float2*)(Cout + (size_t)r0 * N + col)       = v0;
            *(float2*)(Cout + (size_t)(r0 + 8) * N + col) = v1;
        }
    }
}

// ---------------- RoPE + transpose + pack: [B,T,Hn,HD] -> packed [B,Hn,T,64] ----------------
__global__ void rope_pack_kernel(const float* __restrict__ in, const float* __restrict__ cosp,
                                 const float* __restrict__ sinp, unsigned* __restrict__ oh,
                                 unsigned* __restrict__ ol, int Hn) {
    int idx = blockIdx.x * blockDim.x + threadIdx.x;
    int total = B_ * T_ * Hn * 32;
    if (idx >= total) return;
    int d2 = idx & 31;
    int h  = (idx >> 5) % Hn;
    int t  = (idx >> 5) / Hn % T_;
    int b  = (idx >> 5) / Hn / T_;
    size_t ib = ((size_t)(b * T_ + t) * Hn + h) * HD_ + 2 * d2;
    float2 x01 = *(const float2*)(in + ib);
    float2 x23 = *(const float2*)(in + ib + 64);
    size_t cb = (size_t)(b * T_ + t) * HD_ + 2 * d2;
    float2 c01 = *(const float2*)(cosp + cb), c23 = *(const float2*)(cosp + cb + 64);
    float2 s01 = *(const float2*)(sinp + cb), s23 = *(const float2*)(sinp + cb + 64);
    float o0 = x01.x * c01.x - x23.x * s01.x;
    float o1 = x01.y * c01.y - x23.y * s01.y;
    float o2 = x23.x * c23.x + x01.x * s23.x;
    float o3 = x23.y * c23.y + x01.y * s23.y;
    size_t ob = ((size_t)(b * Hn + h) * T_ + t) * 64 + d2;
    unsigned hA, lA, hB, lB;
    split2(o0, o1, hA, lA);
    split2(o2, o3, hB, lB);
    oh[ob] = hA;  ol[ob] = lA;
    oh[ob + 32] = hB;  ol[ob + 32] = lB;
}

// ---------------- pack V: [B,T,HK,HD] -> [B,HK,T/2,HD] u32 (pairs along T) ----------------
__global__ void pack_v_kernel(const float* __restrict__ in, unsigned* __restrict__ oh,
                              unsigned* __restrict__ ol) {
    int idx = blockIdx.x * blockDim.x + threadIdx.x;
    int total = B_ * HK_ * (T_/2) * 32;
    if (idx >= total) return;
    int d4 = (idx & 31) * 4;
    int tp = (idx >> 5) % (T_/2);
    int hk = (idx >> 5) / (T_/2) % HK_;
    int b  = (idx >> 5) / (T_/2) / HK_;
    float4 r0 = *(const float4*)(in + ((size_t)(b * T_ + 2*tp)     * HK_ + hk) * HD_ + d4);
    float4 r1 = *(const float4*)(in + ((size_t)(b * T_ + 2*tp + 1) * HK_ + hk) * HD_ + d4);
    uint4 h, l;
    split2(r0.x, r1.x, h.x, l.x);  split2(r0.y, r1.y, h.y, l.y);
    split2(r0.z, r1.z, h.z, l.z);  split2(r0.w, r1.w, h.w, l.w);
    size_t ob = ((size_t)(b * HK_ + hk) * (T_/2) + tp) * 128 + d4;
    *(uint4*)(oh + ob) = h;
    *(uint4*)(ol + ob) = l;
}

// ---------------- flash attention, pre-packed bf16x3 mma ----------------
// smem offsets in 4-byte units
#define AT_QH 0
#define AT_QL (AT_QH + 64*68)
#define AT_KH (AT_QL + 64*68)
#define AT_KL (AT_KH + 64*68)
#define AT_VH (AT_KL + 64*68)
#define AT_VL (AT_VH + 32*132)
#define AT_SS (AT_VL + 32*132)
#define AT_PH (AT_SS + 64*68)
#define AT_PL (AT_PH + 64*36)
#define AT_RM (AT_PL + 64*36)
#define AT_U32 (AT_RM + 192)
#define AT_BYTES (AT_U32 * 4)

__global__ __launch_bounds__(256) void attn_pk_kernel(
    const unsigned* __restrict__ qh, const unsigned* __restrict__ ql,
    const unsigned* __restrict__ kh, const unsigned* __restrict__ kl,
    const unsigned* __restrict__ vh, const unsigned* __restrict__ vl,
    float* __restrict__ gy)
{
    extern __shared__ unsigned su[];
    unsigned* Qh = su + AT_QH;  unsigned* Ql = su + AT_QL;   // [64][68]: [row][hd_pair]
    unsigned* Kh = su + AT_KH;  unsigned* Kl = su + AT_KL;   // [64][68]: [hd_pair][key]
    unsigned* Vh = su + AT_VH;  unsigned* Vl = su + AT_VL;   // [32][132]: [key_pair][d]
    float*    Ss = (float*)(su + AT_SS);                     // [64][68]
    unsigned* Ph = su + AT_PH;  unsigned* Pl = su + AT_PL;   // [64][36]: [row][key_pair]
    float*  rowm = (float*)(su + AT_RM);
    float*  rowl = rowm + 64;
    float* rowsc = rowl + 64;

    const int qt = blockIdx.x, h = blockIdx.y, b = blockIdx.z;
    const int grp = h >> 2;
    const int tid = threadIdx.x, lane = tid & 31, warp = tid >> 5;
    const int gg = lane >> 2, tg = lane & 3;
    const int wmS = (warp & 3) * 16, wnS = (warp >> 2) * 32;
    const int wnP = (warp >> 2) * 64;
    const float SC = 0.08838834764831845f;

    const unsigned* qbh = qh + (((size_t)b * H_ + h) * T_ + (size_t)qt * 64) * 64;
    const unsigned* qbl = ql + (((size_t)b * H_ + h) * T_ + (size_t)qt * 64) * 64;
    const unsigned* kbh = kh + ((size_t)b * HK_ + grp) * T_ * 64;
    const unsigned* kbl = kl + ((size_t)b * HK_ + grp) * T_ * 64;
    const unsigned* vbh = vh + ((size_t)b * HK_ + grp) * (T_/2) * 128;
    const unsigned* vbl = vl + ((size_t)b * HK_ + grp) * (T_/2) * 128;

    // Q tile: [64 rows][64 pairs] u32, row-major copy
#pragma unroll
    for (int p = 0; p < 4; p++) {
        int idx = tid + p * 256;            // 1024 int4 per matrix
        int row = idx >> 4, c4 = (idx & 15) * 4;
        *(uint4*)&Qh[row * 68 + c4] = *(const uint4*)(qbh + (size_t)row * 64 + c4);
        *(uint4*)&Ql[row * 68 + c4] = *(const uint4*)(qbl + (size_t)row * 64 + c4);
    }
    if (tid < 64) { rowm[tid] = -1e30f; rowl[tid] = 0.f; }

    float c2[8][4];
#pragma unroll
    for (int nt = 0; nt < 8; nt++)
#pragma unroll
        for (int i = 0; i < 4; i++) c2[nt][i] = 0.f;

    for (int kt = 0; kt <= qt; kt++) {
        __syncthreads();
        // K tile: transpose [64 keys][64 pairs] -> Kh[pair][key]
#pragma unroll
        for (int p = 0; p < 4; p++) {
            int idx = tid + p * 256;
            int key = idx >> 4, c4 = (idx & 15) * 4;
            uint4 a = *(const uint4*)(kbh + ((size_t)kt * 64 + key) * 64 + c4);
            uint4 bb = *(const uint4*)(kbl + ((size_t)kt * 64 + key) * 64 + c4);
            Kh[(c4 + 0) * 68 + key] = a.x;  Kl[(c4 + 0) * 68 + key] = bb.x;
            Kh[(c4 + 1) * 68 + key] = a.y;  Kl[(c4 + 1) * 68 + key] = bb.y;
            Kh[(c4 + 2) * 68 + key] = a.z;  Kl[(c4 + 2) * 68 + key] = bb.z;
            Kh[(c4 + 3) * 68 + key] = a.w;  Kl[(c4 + 3) * 68 + key] = bb.w;
        }
        // V tile: [32 key_pairs][128 d] row-major copy
#pragma unroll
        for (int p = 0; p < 4; p++) {
            int idx = tid + p * 256;
            int row = idx >> 5, c4 = (idx & 31) * 4;
            *(uint4*)&Vh[row * 132 + c4] = *(const uint4*)(vbh + ((size_t)kt * 32 + row) * 128 + c4);
            *(uint4*)&Vl[row * 132 + c4] = *(const uint4*)(vbl + ((size_t)kt * 32 + row) * 128 + c4);
        }
        __syncthreads();

        // ---- S = Q K^T ----
        float cs[4][4];
#pragma unroll
        for (int nt = 0; nt < 4; nt++)
#pragma unroll
            for (int i = 0; i < 4; i++) cs[nt][i] = 0.f;

#pragma unroll
        for (int kp8 = 0; kp8 < 64; kp8 += 8) {
            unsigned ah[4], al[4];
            ah[0] = Qh[(wmS + gg    ) * 68 + kp8 + tg    ];
            ah[1] = Qh[(wmS + gg + 8) * 68 + kp8 + tg    ];
            ah[2] = Qh[(wmS + gg    ) * 68 + kp8 + tg + 4];
            ah[3] = Qh[(wmS + gg + 8) * 68 + kp8 + tg + 4];
            al[0] = Ql[(wmS + gg    ) * 68 + kp8 + tg    ];
            al[1] = Ql[(wmS + gg + 8) * 68 + kp8 + tg    ];
            al[2] = Ql[(wmS + gg    ) * 68 + kp8 + tg + 4];
            al[3] = Ql[(wmS + gg + 8) * 68 + kp8 + tg + 4];
#pragma unroll
            for (int nt = 0; nt < 4; nt++) {
                int cn = wnS + nt * 8 + gg;
                unsigned bh0 = Kh[(kp8 + tg    ) * 68 + cn];
                unsigned bh1 = Kh[(kp8 + tg + 4) * 68 + cn];
                unsigned bl0 = Kl[(kp8 + tg    ) * 68 + cn];
                unsigned bl1 = Kl[(kp8 + tg + 4) * 68 + cn];
                MMA_BF16(cs[nt], ah, bh0, bh1);
                MMA_BF16(cs[nt], al, bh0, bh1);
                MMA_BF16(cs[nt], ah, bl0, bl1);
            }
        }
        {
            int qi0 = qt * 64 + wmS + gg;
            int qi1 = qi0 + 8;
#pragma unroll
            for (int nt = 0; nt < 4; nt++) {
                int col = wnS + nt * 8 + tg * 2;
                int kj = kt * 64 + col;
                Ss[(wmS + gg    ) * 68 + col    ] = (kj     <= qi0) ? cs[nt][0] * SC : -1e30f;
                Ss[(wmS + gg    ) * 68 + col + 1] = (kj + 1 <= qi0) ? cs[nt][1] * SC : -1e30f;
                Ss[(wmS + gg + 8) * 68 + col    ] = (kj     <= qi1) ? cs[nt][2] * SC : -1e30f;
                Ss[(wmS + gg + 8) * 68 + col + 1] = (kj + 1 <= qi1) ? cs[nt][3] * SC : -1e30f;
            }
        }
        __syncthreads();

        // ---- online softmax (4 threads/row) + pack P ----
        {
            int r = tid >> 2, part = tid & 3, base = part * 16;
            float mold = rowm[r];
            float tmax = mold;
            float pv[16];
#pragma unroll
            for (int j = 0; j < 16; j++) { pv[j] = Ss[r * 68 + base + j]; tmax = fmaxf(tmax, pv[j]); }
            tmax = fmaxf(tmax, __shfl_xor_sync(0xFFFFFFFFu, tmax, 1));
            tmax = fmaxf(tmax, __shfl_xor_sync(0xFFFFFFFFu, tmax, 2));
            float sum = 0.f;
#pragma unroll
            for (int j = 0; j < 16; j++) { pv[j] = __expf(pv[j] - tmax); sum += pv[j]; }
            sum += __shfl_xor_sync(0xFFFFFFFFu, sum, 1);
            sum += __shfl_xor_sync(0xFFFFFFFFu, sum, 2);
#pragma unroll
            for (int j = 0; j < 8; j++) {
                unsigned hh, ll;
                split2(pv[2*j], pv[2*j + 1], hh, ll);
                Ph[r * 36 + part * 8 + j] = hh;
                Pl[r * 36 + part * 8 + j] = ll;
            }
            if (part == 0) {
                float sc = __expf(mold - tmax);
                rowsc[r] = sc;
                rowl[r] = rowl[r] * sc + sum;
                rowm[r] = tmax;
            }
        }
        __syncthreads();

        // ---- rescale + PV ----
        {
            float s0 = rowsc[wmS + gg], s1 = rowsc[wmS + gg + 8];
#pragma unroll
            for (int nt = 0; nt < 8; nt++) {
                c2[nt][0] *= s0; c2[nt][1] *= s0;
                c2[nt][2] *= s1; c2[nt][3] *= s1;
            }
        }
#pragma unroll
        for (int kp8 = 0; kp8 < 32; kp8 += 8) {
            unsigned ah[4], al[4];
            ah[0] = Ph[(wmS + gg    ) * 36 + kp8 + tg    ];
            ah[1] = Ph[(wmS + gg + 8) * 36 + kp8 + tg    ];
            ah[2] = Ph[(wmS + gg    ) * 36 + kp8 + tg + 4];
            ah[3] = Ph[(wmS + gg + 8) * 36 + kp8 + tg + 4];
            al[0] = Pl[(wmS + gg    ) * 36 + kp8 + tg    ];
            al[1] = Pl[(wmS + gg + 8) * 36 + kp8 + tg    ];
            al[2] = Pl[(wmS + gg    ) * 36 + kp8 + tg + 4];
            al[3] = Pl[(wmS + gg + 8) * 36 + kp8 + tg + 4];
#pragma unroll
            for (int nt = 0; nt < 8; nt++) {
                int cn = wnP + nt * 8 + gg;
                unsigned bh0 = Vh[(kp8 + tg    ) * 132 + cn];
                unsigned bh1 = Vh[(kp8 + tg + 4) * 132 + cn];
                unsigned bl0 = Vl[(kp8 + tg    ) * 132 + cn];
                unsigned bl1 = Vl[(kp8 + tg + 4) * 132 + cn];
                MMA_BF16(c2[nt], ah, bh0, bh1);
                MMA_BF16(c2[nt], al, bh0, bh1);
                MMA_BF16(c2[nt], ah, bl0, bl1);
            }
        }
    }
    __syncthreads();

    {
        float inv0 = 1.f / rowl[wmS + gg];
        float inv1 = 1.f / rowl[wmS + gg + 8];
        int row0 = qt * 64 + wmS + gg;
#pragma unroll
        for (int nt = 0; nt < 8; nt++) {
            int col = wnP + nt * 8 + tg * 2;
            float* op0 = gy + ((size_t)b * T_ + row0) * C_ + h * HD_ + col;
            float* op1 = gy + ((size_t)b * T_ + row0 + 8) * C_ + h * HD_ + col;
            float2 o0 = {c2[nt][0] * inv0, c2[nt][1] * inv0};
            float2 o1 = {c2[nt][2] * inv1, c2[nt][3] * inv1};
            *(float2*)op0 = o0;
            *(float2*)op1 = o1;
        }
    }
}

// ---------------- launch ----------------
extern "C" void kernel_launch(void* const* d_in, const int* in_sizes, int n_in,
                              void* d_out, int out_size) {
    const float* x    = (const float*)d_in[0];
    const float* cosp = (const float*)d_in[1];
    const float* sinp = (const float*)d_in[2];
    const float* Wq   = (const float*)d_in[3];
    const float* bq   = (const float*)d_in[4];
    const float* Wk   = (const float*)d_in[5];
    const float* bk   = (const float*)d_in[6];
    const float* Wv   = (const float*)d_in[7];
    const float* bv   = (const float*)d_in[8];
    const float* Wo   = (const float*)d_in[9];
    float* out = (float*)d_out;

    float *qt, *ktp, *vtp, *y;
    cudaGetSymbolAddress((void**)&qt,  g_qt);
    cudaGetSymbolAddress((void**)&ktp, g_kt);
    cudaGetSymbolAddress((void**)&vtp, g_vt);
    cudaGetSymbolAddress((void**)&y,   g_y);
    unsigned *xph,*xpl,*yph,*ypl,*wqph,*wqpl,*wkph,*wkpl,*wvph,*wvpl,*woph,*wopl;
    unsigned *qph,*qpl,*kph,*kpl,*vph,*vpl;
    cudaGetSymbolAddress((void**)&xph, g_xph);   cudaGetSymbolAddress((void**)&xpl, g_xpl);
    cudaGetSymbolAddress((void**)&yph, g_yph);   cudaGetSymbolAddress((void**)&ypl, g_ypl);
    cudaGetSymbolAddress((void**)&wqph, g_wqph); cudaGetSymbolAddress((void**)&wqpl, g_wqpl);
    cudaGetSymbolAddress((void**)&wkph, g_wkph); cudaGetSymbolAddress((void**)&wkpl, g_wkpl);
    cudaGetSymbolAddress((void**)&wvph, g_wvph); cudaGetSymbolAddress((void**)&wvpl, g_wvpl);
    cudaGetSymbolAddress((void**)&woph, g_woph); cudaGetSymbolAddress((void**)&wopl, g_wopl);
    cudaGetSymbolAddress((void**)&qph, g_qph);   cudaGetSymbolAddress((void**)&qpl, g_qpl);
    cudaGetSymbolAddress((void**)&kph, g_kph);   cudaGetSymbolAddress((void**)&kpl, g_kpl);
    cudaGetSymbolAddress((void**)&vph, g_vph);   cudaGetSymbolAddress((void**)&vpl, g_vpl);

    // prep
    {
        int n8 = BT_ * C_ / 8;
        split_pack_rows<<<(n8 + 255)/256, 256>>>(x, xph, xpl, n8);
        int nwq = 1024 * 512;   // (K/2)*(N/4) for N=2048
        pack_w<<<(nwq + 255)/256, 256>>>(Wq, wqph, wqpl, C_, 2048);
        int nwk = 1024 * 128;
        pack_w<<<(nwk + 255)/256, 256>>>(Wk, wkph, wkpl, C_, 512);
        pack_w<<<(nwk + 255)/256, 256>>>(Wv, wvph, wvpl, C_, 512);
        pack_w<<<(nwq + 255)/256, 256>>>(Wo, woph, wopl, C_, 2048);
    }

    // QKV projections
    gemm_pk_kernel<<<dim3(16, 32), 256>>>(xph, xpl, wqph, wqpl, bq, qt,  BT_, 2048, 1024);
    gemm_pk_kernel<<<dim3(4,  32), 256>>>(xph, xpl, wkph, wkpl, bk, ktp, BT_, 512,  1024);
    gemm_pk_kernel<<<dim3(4,  32), 256>>>(xph, xpl, wvph, wvpl, bv, vtp, BT_, 512,  1024);

    // RoPE + pack
    {
        int nq = B_ * T_ * H_ * 32;
        rope_pack_kernel<<<(nq + 255)/256, 256>>>(qt, cosp, sinp, qph, qpl, H_);
        int nk = B_ * T_ * HK_ * 32;
        rope_pack_kernel<<<(nk + 255)/256, 256>>>(ktp, cosp, sinp, kph, kpl, HK_);
        int nv = B_ * HK_ * (T_/2) * 32;
        pack_v_kernel<<<(nv + 255)/256, 256>>>(vtp, vph, vpl);
    }

    // attention
    cudaFuncSetAttribute(attn_pk_kernel, cudaFuncAttributeMaxDynamicSharedMemorySize, AT_BYTES);
    attn_pk_kernel<<<dim3(T_/64, H_, B_), 256, AT_BYTES>>>(qph, qpl, kph, kpl, vph, vpl, y);

    // out projection
    {
        int n8 = BT_ * C_ / 8;
        split_pack_rows<<<(n8 + 255)/256, 256>>>(y, yph, ypl, n8);
        gemm_pk_kernel<<<dim3(16, 32), 256>>>(yph, ypl, woph, wopl, nullptr, out, BT_, C_, 1024);
    }
}

// round 13
// speedup vs baseline: 3.1339x; 1.0759x over previous
#include <cuda_runtime.h>
#include <cuda_bf16.h>
#include <cstddef>

#define B_  2
#define T_  2048
#define C_  2048
#define H_  16
#define HK_ 4
#define HD_ 128
#define BT_ (B_*T_)

// fp32 intermediates
__device__ float g_qt[(size_t)BT_ * 2048];
__device__ float g_kt[(size_t)BT_ * 512];
__device__ float g_vt[(size_t)BT_ * 512];
__device__ float g_y [(size_t)BT_ * C_];
// packed bf16 hi/lo operands
__device__ unsigned g_xph[(size_t)BT_ * 1024], g_xpl[(size_t)BT_ * 1024];
__device__ unsigned g_yph[(size_t)BT_ * 1024], g_ypl[(size_t)BT_ * 1024];
__device__ unsigned g_wqph[(size_t)1024 * 2048], g_wqpl[(size_t)1024 * 2048];
__device__ unsigned g_wkph[(size_t)1024 * 512],  g_wkpl[(size_t)1024 * 512];
__device__ unsigned g_wvph[(size_t)1024 * 512],  g_wvpl[(size_t)1024 * 512];
__device__ unsigned g_woph[(size_t)1024 * 2048], g_wopl[(size_t)1024 * 2048];
__device__ unsigned g_qph[(size_t)B_*H_ *T_*64], g_qpl[(size_t)B_*H_ *T_*64];
__device__ unsigned g_kph[(size_t)B_*HK_*64*T_], g_kpl[(size_t)B_*HK_*64*T_];  // pair-major [b,hk,pair,t]
__device__ unsigned g_vph[(size_t)B_*HK_*(T_/2)*128], g_vpl[(size_t)B_*HK_*(T_/2)*128];

#define MMA_BF16(Cacc, Af, b0, b1)                                                 \
    asm volatile("mma.sync.aligned.m16n8k16.row.col.f32.bf16.bf16.f32 "            \
        "{%0,%1,%2,%3}, {%4,%5,%6,%7}, {%8,%9}, {%0,%1,%2,%3};"                    \
        : "+f"(Cacc[0]), "+f"(Cacc[1]), "+f"(Cacc[2]), "+f"(Cacc[3])               \
        : "r"(Af[0]), "r"(Af[1]), "r"(Af[2]), "r"(Af[3]), "r"(b0), "r"(b1))

__device__ __forceinline__ void split2(float a, float b, unsigned& h, unsigned& l) {
    __nv_bfloat162 hb = __floats2bfloat162_rn(a, b);
    float ha = __bfloat162float(hb.x), hbv = __bfloat162float(hb.y);
    __nv_bfloat162 lb = __floats2bfloat162_rn(a - ha, b - hbv);
    h = *reinterpret_cast<unsigned*>(&hb);
    l = *reinterpret_cast<unsigned*>(&lb);
}

// ---------------- prep kernels ----------------
__global__ void split_pack_rows(const float* __restrict__ in, unsigned* __restrict__ oh,
                                unsigned* __restrict__ ol, int n8) {
    int i = blockIdx.x * blockDim.x + threadIdx.x;
    if (i >= n8) return;
    float4 a = ((const float4*)in)[2*i], b = ((const float4*)in)[2*i + 1];
    uint4 h, l;
    split2(a.x, a.y, h.x, l.x);  split2(a.z, a.w, h.y, l.y);
    split2(b.x, b.y, h.z, l.z);  split2(b.z, b.w, h.w, l.w);
    ((uint4*)oh)[i] = h;  ((uint4*)ol)[i] = l;
}

__global__ void pack_w(const float* __restrict__ W, unsigned* __restrict__ oh,
                       unsigned* __restrict__ ol, int K, int N) {
    int i = blockIdx.x * blockDim.x + threadIdx.x;
    int n4q = N >> 2;
    if (i >= (K/2) * n4q) return;
    int kp = i / n4q, n4 = (i % n4q) * 4;
    float4 r0 = *(const float4*)(W + (size_t)(2*kp)     * N + n4);
    float4 r1 = *(const float4*)(W + (size_t)(2*kp + 1) * N + n4);
    uint4 h, l;
    split2(r0.x, r1.x, h.x, l.x);  split2(r0.y, r1.y, h.y, l.y);
    split2(r0.z, r1.z, h.z, l.z);  split2(r0.w, r1.w, h.w, l.w);
    *(uint4*)(oh + (size_t)kp * N + n4) = h;
    *(uint4*)(ol + (size_t)kp * N + n4) = l;
}

// ---------------- 3xBF16 GEMM on pre-packed operands (unchanged) ----------------
__global__ __launch_bounds__(256) void gemm_pk_kernel(
    const unsigned* __restrict__ Aph, const unsigned* __restrict__ Apl,
    const unsigned* __restrict__ Wph, const unsigned* __restrict__ Wpl,
    const float* __restrict__ bias, float* __restrict__ Cout,
    int M, int N, int Kp)
{
    __shared__ unsigned Ah[128][12], Al[128][12];
    __shared__ unsigned Wh[8][136],  Wl[8][136];

    const int tid  = threadIdx.x;
    const int bm   = blockIdx.y * 128, bn = blockIdx.x * 128;
    const int lane = tid & 31, warp = tid >> 5;
    const int wm   = (warp & 3) * 32, wn = (warp >> 2) * 64;
    const int g    = lane >> 2, tg = lane & 3;

    const int arow = tid >> 1, ahalf = (tid & 1) * 4;
    const int wkp  = tid >> 5, wn4   = (tid & 31) * 4;

    uint4 aH, aL, wH, wL;
    float c[2][8][4];
#pragma unroll
    for (int mt = 0; mt < 2; mt++)
#pragma unroll
        for (int nt = 0; nt < 8; nt++)
#pragma unroll
            for (int i = 0; i < 4; i++) c[mt][nt][i] = 0.f;

    auto loadG = [&](int kp0) {
        aH = *(const uint4*)(Aph + (size_t)(bm + arow) * Kp + kp0 + ahalf);
        aL = *(const uint4*)(Apl + (size_t)(bm + arow) * Kp + kp0 + ahalf);
        wH = *(const uint4*)(Wph + (size_t)(kp0 + wkp) * N + bn + wn4);
        wL = *(const uint4*)(Wpl + (size_t)(kp0 + wkp) * N + bn + wn4);
    };
    auto storeS = [&]() {
        *(uint4*)&Ah[arow][ahalf] = aH;
        *(uint4*)&Al[arow][ahalf] = aL;
        *(uint4*)&Wh[wkp][wn4]    = wH;
        *(uint4*)&Wl[wkp][wn4]    = wL;
    };
    auto computeTile = [&]() {
        unsigned ah[2][4], al[2][4];
#pragma unroll
        for (int mt = 0; mt < 2; mt++) {
            int r = wm + mt * 16;
            ah[mt][0] = Ah[r + g    ][tg];
            ah[mt][1] = Ah[r + g + 8][tg];
            ah[mt][2] = Ah[r + g    ][tg + 4];
            ah[mt][3] = Ah[r + g + 8][tg + 4];
            al[mt][0] = Al[r + g    ][tg];
            al[mt][1] = Al[r + g + 8][tg];
            al[mt][2] = Al[r + g    ][tg + 4];
            al[mt][3] = Al[r + g + 8][tg + 4];
        }
#pragma unroll
        for (int nt = 0; nt < 8; nt++) {
            int cn = wn + nt * 8 + g;
            unsigned bh0 = Wh[tg][cn], bh1 = Wh[tg + 4][cn];
            unsigned bl0 = Wl[tg][cn], bl1 = Wl[tg + 4][cn];
#pragma unroll
            for (int mt = 0; mt < 2; mt++) {
                MMA_BF16(c[mt][nt], ah[mt], bh0, bh1);
                MMA_BF16(c[mt][nt], al[mt], bh0, bh1);
                MMA_BF16(c[mt][nt], ah[mt], bl0, bl1);
            }
        }
    };

    loadG(0);
    storeS();
    __syncthreads();
    for (int kp0 = 8; kp0 < Kp; kp0 += 8) {
        loadG(kp0);
        computeTile();
        __syncthreads();
        storeS();
        __syncthreads();
    }
    computeTile();

#pragma unroll
    for (int mt = 0; mt < 2; mt++) {
        int r0 = bm + wm + mt * 16 + g;
#pragma unroll
        for (int nt = 0; nt < 8; nt++) {
            int col = bn + wn + nt * 8 + tg * 2;
            float b0 = 0.f, b1 = 0.f;
            if (bias) { b0 = bias[col]; b1 = bias[col + 1]; }
            float2 v0 = {c[mt][nt][0] + b0, c[mt][nt][1] + b1};
            float2 v1 = {c[mt][nt][2] + b0, c[mt][nt][3] + b1};
            *(float2*)(Cout + (size_t)r0 * N + col)       = v0;
            *(float2*)(Cout + (size_t)(r0 + 8) * N + col) = v1;
        }
    }
}

// ---------------- RoPE + pack Q: [B,T,H,HD] -> [B,H,T,64] pairs along HD ----------------
__global__ void rope_pack_kernel(const float* __restrict__ in, const float* __restrict__ cosp,
                                 const float* __restrict__ sinp, unsigned* __restrict__ oh,
                                 unsigned* __restrict__ ol, int Hn) {
    int idx = blockIdx.x * blockDim.x + threadIdx.x;
    int total = B_ * T_ * Hn * 32;
    if (idx >= total) return;
    int d2 = idx & 31;
    int h  = (idx >> 5) % Hn;
    int t  = (idx >> 5) / Hn % T_;
    int b  = (idx >> 5) / Hn / T_;
    size_t ib = ((size_t)(b * T_ + t) * Hn + h) * HD_ + 2 * d2;
    float2 x01 = *(const float2*)(in + ib);
    float2 x23 = *(const float2*)(in + ib + 64);
    size_t cb = (size_t)(b * T_ + t) * HD_ + 2 * d2;
    float2 c01 = *(const float2*)(cosp + cb), c23 = *(const float2*)(cosp + cb + 64);
    float2 s01 = *(const float2*)(sinp + cb), s23 = *(const float2*)(sinp + cb + 64);
    float o0 = x01.x * c01.x - x23.x * s01.x;
    float o1 = x01.y * c01.y - x23.y * s01.y;
    float o2 = x23.x * c23.x + x01.x * s23.x;
    float o3 = x23.y * c23.y + x01.y * s23.y;
    size_t ob = ((size_t)(b * Hn + h) * T_ + t) * 64 + d2;
    unsigned hA, lA, hB, lB;
    split2(o0, o1, hA, lA);
    split2(o2, o3, hB, lB);
    oh[ob] = hA;  ol[ob] = lA;
    oh[ob + 32] = hB;  ol[ob + 32] = lB;
}

// ---------------- RoPE + pack K transposed: [B,T,HK,HD] -> [B,HK,64pair,T] ----------------
__global__ void rope_pack_kt_kernel(const float* __restrict__ in, const float* __restrict__ cosp,
                                    const float* __restrict__ sinp, unsigned* __restrict__ oh,
                                    unsigned* __restrict__ ol) {
    int idx = blockIdx.x * blockDim.x + threadIdx.x;
    int total = B_ * T_ * HK_ * 32;
    if (idx >= total) return;
    int d2 = idx & 31;
    int h  = (idx >> 5) % HK_;
    int t  = (idx >> 5) / HK_ % T_;
    int b  = (idx >> 5) / HK_ / T_;
    size_t ib = ((size_t)(b * T_ + t) * HK_ + h) * HD_ + 2 * d2;
    float2 x01 = *(const float2*)(in + ib);
    float2 x23 = *(const float2*)(in + ib + 64);
    size_t cb = (size_t)(b * T_ + t) * HD_ + 2 * d2;
    float2 c01 = *(const float2*)(cosp + cb), c23 = *(const float2*)(cosp + cb + 64);
    float2 s01 = *(const float2*)(sinp + cb), s23 = *(const float2*)(sinp + cb + 64);
    float o0 = x01.x * c01.x - x23.x * s01.x;
    float o1 = x01.y * c01.y - x23.y * s01.y;
    float o2 = x23.x * c23.x + x01.x * s23.x;
    float o3 = x23.y * c23.y + x01.y * s23.y;
    unsigned hA, lA, hB, lB;
    split2(o0, o1, hA, lA);
    split2(o2, o3, hB, lB);
    size_t ob = ((size_t)(b * HK_ + h) * 64 + d2) * T_ + t;
    oh[ob] = hA;  ol[ob] = lA;
    oh[ob + (size_t)32 * T_] = hB;  ol[ob + (size_t)32 * T_] = lB;
}

// ---------------- pack V: [B,T,HK,HD] -> [B,HK,T/2,HD] pairs along T ----------------
__global__ void pack_v_kernel(const float* __restrict__ in, unsigned* __restrict__ oh,
                              unsigned* __restrict__ ol) {
    int idx = blockIdx.x * blockDim.x + threadIdx.x;
    int total = B_ * HK_ * (T_/2) * 32;
    if (idx >= total) return;
    int d4 = (idx & 31) * 4;
    int tp = (idx >> 5) % (T_/2);
    int hk = (idx >> 5) / (T_/2) % HK_;
    int b  = (idx >> 5) / (T_/2) / HK_;
    float4 r0 = *(const float4*)(in + ((size_t)(b * T_ + 2*tp)     * HK_ + hk) * HD_ + d4);
    float4 r1 = *(const float4*)(in + ((size_t)(b * T_ + 2*tp + 1) * HK_ + hk) * HD_ + d4);
    uint4 h, l;
    split2(r0.x, r1.x, h.x, l.x);  split2(r0.y, r1.y, h.y, l.y);
    split2(r0.z, r1.z, h.z, l.z);  split2(r0.w, r1.w, h.w, l.w);
    size_t ob = ((size_t)(b * HK_ + hk) * (T_/2) + tp) * 128 + d4;
    *(uint4*)(oh + ob) = h;
    *(uint4*)(ol + ob) = l;
}

// ---------------- flash attention: 128-row Q tiles, pre-packed bf16x3 ----------------
// smem (u32 units)
#define AT_QH 0
#define AT_QL (AT_QH + 128*68)
#define AT_KH (AT_QL + 128*68)
#define AT_KL (AT_KH + 64*68)
#define AT_VH (AT_KL + 64*68)
#define AT_VL (AT_VH + 32*132)
#define AT_SS (AT_VL + 32*132)
#define AT_PH (AT_SS + 128*68)
#define AT_PL (AT_PH + 128*36)
#define AT_RM (AT_PL + 128*36)
#define AT_U32 (AT_RM + 384)
#define AT_BYTES (AT_U32 * 4)

__global__ __launch_bounds__(256) void attn_pk_kernel(
    const unsigned* __restrict__ qh, const unsigned* __restrict__ ql,
    const unsigned* __restrict__ kh, const unsigned* __restrict__ kl,
    const unsigned* __restrict__ vh, const unsigned* __restrict__ vl,
    float* __restrict__ gy)
{
    extern __shared__ unsigned su[];
    unsigned* Qh = su + AT_QH;  unsigned* Ql = su + AT_QL;   // [128][68]: [row][hd_pair]
    unsigned* Kh = su + AT_KH;  unsigned* Kl = su + AT_KL;   // [64][68]:  [hd_pair][key]
    unsigned* Vh = su + AT_VH;  unsigned* Vl = su + AT_VL;   // [32][132]: [key_pair][d]
    float*    Ss = (float*)(su + AT_SS);                     // [128][68]
    unsigned* Ph = su + AT_PH;  unsigned* Pl = su + AT_PL;   // [128][36]: [row][key_pair]
    float*  rowm = (float*)(su + AT_RM);
    float*  rowl = rowm + 128;
    float* rowsc = rowl + 128;

    const int qt = (gridDim.x - 1) - blockIdx.x;   // long CTAs first
    const int h = blockIdx.y, b = blockIdx.z;
    const int grp = h >> 2;
    const int tid = threadIdx.x, lane = tid & 31, warp = tid >> 5;
    const int gg = lane >> 2, tg = lane & 3;
    const int wm = warp * 16;                      // 8 warps x 16 rows = 128
    const float SC = 0.08838834764831845f;

    const unsigned* qbh = qh + (((size_t)b * H_ + h) * T_ + (size_t)qt * 128) * 64;
    const unsigned* qbl = ql + (((size_t)b * H_ + h) * T_ + (size_t)qt * 128) * 64;
    const unsigned* kbh = kh + ((size_t)b * HK_ + grp) * 64 * T_;
    const unsigned* kbl = kl + ((size_t)b * HK_ + grp) * 64 * T_;
    const unsigned* vbh = vh + ((size_t)b * HK_ + grp) * (T_/2) * 128;
    const unsigned* vbl = vl + ((size_t)b * HK_ + grp) * (T_/2) * 128;

    // Q tile: [128 rows][64 pairs]
#pragma unroll
    for (int p = 0; p < 8; p++) {
        int idx = tid + p * 256;                 // 2048 uint4 per matrix
        int row = idx >> 4, c4 = (idx & 15) * 4;
        *(uint4*)&Qh[row * 68 + c4] = *(const uint4*)(qbh + (size_t)row * 64 + c4);
        *(uint4*)&Ql[row * 68 + c4] = *(const uint4*)(qbl + (size_t)row * 64 + c4);
    }
    if (tid < 128) { rowm[tid] = -1e30f; rowl[tid] = 0.f; }

    float c2[16][4];
#pragma unroll
    for (int nt = 0; nt < 16; nt++)
#pragma unroll
        for (int i = 0; i < 4; i++) c2[nt][i] = 0.f;

    const int nkt = 2 * qt + 2;
    for (int kt = 0; kt < nkt; kt++) {
        __syncthreads();
        // K tile: [64 pair rows][64 keys], coalesced rows (global already transposed)
#pragma unroll
        for (int p = 0; p < 4; p++) {
            int idx = tid + p * 256;             // 1024 uint4 per matrix
            int pr = idx >> 4, c4 = (idx & 15) * 4;
            *(uint4*)&Kh[pr * 68 + c4] = *(const uint4*)(kbh + (size_t)pr * T_ + kt * 64 + c4);
            *(uint4*)&Kl[pr * 68 + c4] = *(const uint4*)(kbl + (size_t)pr * T_ + kt * 64 + c4);
        }
        // V tile: [32 key_pairs][128 d]
#pragma unroll
        for (int p = 0; p < 4; p++) {
            int idx = tid + p * 256;
            int row = idx >> 5, c4 = (idx & 31) * 4;
            *(uint4*)&Vh[row * 132 + c4] = *(const uint4*)(vbh + ((size_t)kt * 32 + row) * 128 + c4);
            *(uint4*)&Vl[row * 132 + c4] = *(const uint4*)(vbl + ((size_t)kt * 32 + row) * 128 + c4);
        }
        __syncthreads();

        // ---- S = Q K^T : each warp 16 rows x 64 cols ----
        float cs[8][4];
#pragma unroll
        for (int nt = 0; nt < 8; nt++)
#pragma unroll
            for (int i = 0; i < 4; i++) cs[nt][i] = 0.f;

#pragma unroll
        for (int kp8 = 0; kp8 < 64; kp8 += 8) {
            unsigned ah[4], al[4];
            ah[0] = Qh[(wm + gg    ) * 68 + kp8 + tg    ];
            ah[1] = Qh[(wm + gg + 8) * 68 + kp8 + tg    ];
            ah[2] = Qh[(wm + gg    ) * 68 + kp8 + tg + 4];
            ah[3] = Qh[(wm + gg + 8) * 68 + kp8 + tg + 4];
            al[0] = Ql[(wm + gg    ) * 68 + kp8 + tg    ];
            al[1] = Ql[(wm + gg + 8) * 68 + kp8 + tg    ];
            al[2] = Ql[(wm + gg    ) * 68 + kp8 + tg + 4];
            al[3] = Ql[(wm + gg + 8) * 68 + kp8 + tg + 4];
#pragma unroll
            for (int nt = 0; nt < 8; nt++) {
                int cn = nt * 8 + gg;
                unsigned bh0 = Kh[(kp8 + tg    ) * 68 + cn];
                unsigned bh1 = Kh[(kp8 + tg + 4) * 68 + cn];
                unsigned bl0 = Kl[(kp8 + tg    ) * 68 + cn];
                unsigned bl1 = Kl[(kp8 + tg + 4) * 68 + cn];
                MMA_BF16(cs[nt], ah, bh0, bh1);
                MMA_BF16(cs[nt], al, bh0, bh1);
                MMA_BF16(cs[nt], ah, bl0, bl1);
            }
        }
        {
            int qi0 = qt * 128 + wm + gg;
            int qi1 = qi0 + 8;
#pragma unroll
            for (int nt = 0; nt < 8; nt++) {
                int col = nt * 8 + tg * 2;
                int kj = kt * 64 + col;
                Ss[(wm + gg    ) * 68 + col    ] = (kj     <= qi0) ? cs[nt][0] * SC : -1e30f;
                Ss[(wm + gg    ) * 68 + col + 1] = (kj + 1 <= qi0) ? cs[nt][1] * SC : -1e30f;
                Ss[(wm + gg + 8) * 68 + col    ] = (kj     <= qi1) ? cs[nt][2] * SC : -1e30f;
                Ss[(wm + gg + 8) * 68 + col + 1] = (kj + 1 <= qi1) ? cs[nt][3] * SC : -1e30f;
            }
        }
        __syncthreads();

        // ---- online softmax (2 threads/row) + pack P ----
        {
            int r = tid >> 1, part = tid & 1, base = part * 32;
            float mold = rowm[r];
            float tmax = mold;
            float pv[32];
#pragma unroll
            for (int j = 0; j < 32; j++) { pv[j] = Ss[r * 68 + base + j]; tmax = fmaxf(tmax, pv[j]); }
            tmax = fmaxf(tmax, __shfl_xor_sync(0xFFFFFFFFu, tmax, 1));
            float sum = 0.f;
#pragma unroll
            for (int j = 0; j < 32; j++) { pv[j] = __expf(pv[j] - tmax); sum += pv[j]; }
            sum += __shfl_xor_sync(0xFFFFFFFFu, sum, 1);
#pragma unroll
            for (int j = 0; j < 16; j++) {
                unsigned hh, ll;
                split2(pv[2*j], pv[2*j + 1], hh, ll);
                Ph[r * 36 + part * 16 + j] = hh;
                Pl[r * 36 + part * 16 + j] = ll;
            }
            if (part == 0) {
                float sc = __expf(mold - tmax);
                rowsc[r] = sc;
                rowl[r] = rowl[r] * sc + sum;
                rowm[r] = tmax;
            }
        }
        __syncthreads();

        // ---- rescale + PV: each warp 16 rows x 128 cols ----
        {
            float s0 = rowsc[wm + gg], s1 = rowsc[wm + gg + 8];
#pragma unroll
            for (int nt = 0; nt < 16; nt++) {
                c2[nt][0] *= s0; c2[nt][1] *= s0;
                c2[nt][2] *= s1; c2[nt][3] *= s1;
            }
        }
#pragma unroll
        for (int kp8 = 0; kp8 < 32; kp8 += 8) {
            unsigned ah[4], al[4];
            ah[0] = Ph[(wm + gg    ) * 36 + kp8 + tg    ];
            ah[1] = Ph[(wm + gg + 8) * 36 + kp8 + tg    ];
            ah[2] = Ph[(wm + gg    ) * 36 + kp8 + tg + 4];
            ah[3] = Ph[(wm + gg + 8) * 36 + kp8 + tg + 4];
            al[0] = Pl[(wm + gg    ) * 36 + kp8 + tg    ];
            al[1] = Pl[(wm + gg + 8) * 36 + kp8 + tg    ];
            al[2] = Pl[(wm + gg    ) * 36 + kp8 + tg + 4];
            al[3] = Pl[(wm + gg + 8) * 36 + kp8 + tg + 4];
#pragma unroll
            for (int nt = 0; nt < 16; nt++) {
                int cn = nt * 8 + gg;
                unsigned bh0 = Vh[(kp8 + tg    ) * 132 + cn];
                unsigned bh1 = Vh[(kp8 + tg + 4) * 132 + cn];
                unsigned bl0 = Vl[(kp8 + tg    ) * 132 + cn];
                unsigned bl1 = Vl[(kp8 + tg + 4) * 132 + cn];
                MMA_BF16(c2[nt], ah, bh0, bh1);
                MMA_BF16(c2[nt], al, bh0, bh1);
                MMA_BF16(c2[nt], ah, bl0, bl1);
            }
        }
    }
    __syncthreads();

    {
        float inv0 = 1.f / rowl[wm + gg];
        float inv1 = 1.f / rowl[wm + gg + 8];
        int row0 = qt * 128 + wm + gg;
#pragma unroll
        for (int nt = 0; nt < 16; nt++) {
            int col = nt * 8 + tg * 2;
            float* op0 = gy + ((size_t)b * T_ + row0) * C_ + h * HD_ + col;
            float* op1 = gy + ((size_t)b * T_ + row0 + 8) * C_ + h * HD_ + col;
            float2 o0 = {c2[nt][0] * inv0, c2[nt][1] * inv0};
            float2 o1 = {c2[nt][2] * inv1, c2[nt][3] * inv1};
            *(float2*)op0 = o0;
            *(float2*)op1 = o1;
        }
    }
}

// ---------------- launch ----------------
extern "C" void kernel_launch(void* const* d_in, const int* in_sizes, int n_in,
                              void* d_out, int out_size) {
    const float* x    = (const float*)d_in[0];
    const float* cosp = (const float*)d_in[1];
    const float* sinp = (const float*)d_in[2];
    const float* Wq   = (const float*)d_in[3];
    const float* bq   = (const float*)d_in[4];
    const float* Wk   = (const float*)d_in[5];
    const float* bk   = (const float*)d_in[6];
    const float* Wv   = (const float*)d_in[7];
    const float* bv   = (const float*)d_in[8];
    const float* Wo   = (const float*)d_in[9];
    float* out = (float*)d_out;

    float *qt, *ktp, *vtp, *y;
    cudaGetSymbolAddress((void**)&qt,  g_qt);
    cudaGetSymbolAddress((void**)&ktp, g_kt);
    cudaGetSymbolAddress((void**)&vtp, g_vt);
    cudaGetSymbolAddress((void**)&y,   g_y);
    unsigned *xph,*xpl,*yph,*ypl,*wqph,*wqpl,*wkph,*wkpl,*wvph,*wvpl,*woph,*wopl;
    unsigned *qph,*qpl,*kph,*kpl,*vph,*vpl;
    cudaGetSymbolAddress((void**)&xph, g_xph);   cudaGetSymbolAddress((void**)&xpl, g_xpl);
    cudaGetSymbolAddress((void**)&yph, g_yph);   cudaGetSymbolAddress((void**)&ypl, g_ypl);
    cudaGetSymbolAddress((void**)&wqph, g_wqph); cudaGetSymbolAddress((void**)&wqpl, g_wqpl);
    cudaGetSymbolAddress((void**)&wkph, g_wkph); cudaGetSymbolAddress((void**)&wkpl, g_wkpl);
    cudaGetSymbolAddress((void**)&wvph, g_wvph); cudaGetSymbolAddress((void**)&wvpl, g_wvpl);
    cudaGetSymbolAddress((void**)&woph, g_woph); cudaGetSymbolAddress((void**)&wopl, g_wopl);
    cudaGetSymbolAddress((void**)&qph, g_qph);   cudaGetSymbolAddress((void**)&qpl, g_qpl);
    cudaGetSymbolAddress((void**)&kph, g_kph);   cudaGetSymbolAddress((void**)&kpl, g_kpl);
    cudaGetSymbolAddress((void**)&vph, g_vph);   cudaGetSymbolAddress((void**)&vpl, g_vpl);

    // prep
    {
        int n8 = BT_ * C_ / 8;
        split_pack_rows<<<(n8 + 255)/256, 256>>>(x, xph, xpl, n8);
        int nwq = 1024 * 512;
        pack_w<<<(nwq + 255)/256, 256>>>(Wq, wqph, wqpl, C_, 2048);
        int nwk = 1024 * 128;
        pack_w<<<(nwk + 255)/256, 256>>>(Wk, wkph, wkpl, C_, 512);
        pack_w<<<(nwk + 255)/256, 256>>>(Wv, wvph, wvpl, C_, 512);
        pack_w<<<(nwq + 255)/256, 256>>>(Wo, woph, wopl, C_, 2048);
    }

    // QKV projections
    gemm_pk_kernel<<<dim3(16, 32), 256>>>(xph, xpl, wqph, wqpl, bq, qt,  BT_, 2048, 1024);
    gemm_pk_kernel<<<dim3(4,  32), 256>>>(xph, xpl, wkph, wkpl, bk, ktp, BT_, 512,  1024);
    gemm_pk_kernel<<<dim3(4,  32), 256>>>(xph, xpl, wvph, wvpl, bv, vtp, BT_, 512,  1024);

    // RoPE + pack
    {
        int nq = B_ * T_ * H_ * 32;
        rope_pack_kernel<<<(nq + 255)/256, 256>>>(qt, cosp, sinp, qph, qpl, H_);
        int nk = B_ * T_ * HK_ * 32;
        rope_pack_kt_kernel<<<(nk + 255)/256, 256>>>(ktp, cosp, sinp, kph, kpl);
        int nv = B_ * HK_ * (T_/2) * 32;
        pack_v_kernel<<<(nv + 255)/256, 256>>>(vtp, vph, vpl);
    }

    // attention (128-row Q tiles)
    cudaFuncSetAttribute(attn_pk_kernel, cudaFuncAttributeMaxDynamicSharedMemorySize, AT_BYTES);
    attn_pk_kernel<<<dim3(T_/128, H_, B_), 256, AT_BYTES>>>(qph, qpl, kph, kpl, vph, vpl, y);

    // out projection
    {
        int n8 = BT_ * C_ / 8;
        split_pack_rows<<<(n8 + 255)/256, 256>>>(y, yph, ypl, n8);
        gemm_pk_kernel<<<dim3(16, 32), 256>>>(yph, ypl, woph, wopl, nullptr, out, BT_, C_, 1024);
    }
}